// round 6
// baseline (speedup 1.0000x reference)
#include <cuda_runtime.h>
#include <math.h>

// Problem constants
#define B_   2
#define L_   2048
#define D_   1024
#define H_   16
#define HD_  64
#define ROWS (B_ * L_)          // 4096
#define D3   (3 * D_)           // 3072
#define D4   (4 * D_)           // 4096

// ---------------------------------------------------------------------------
// Scratch (static __device__ arrays — no allocation allowed)
// ---------------------------------------------------------------------------
__device__ float g_x  [ROWS * D_];   // x = zH + zL, later x2 = x + attn proj
__device__ float g_h  [ROWS * D_];   // rmsnorm output (reused for h2)
__device__ float g_qkv[ROWS * D3];   // qkv projections
__device__ float g_ao [ROWS * D_];   // attention output (b,l,h,d) flattened
__device__ float g_mid[ROWS * D4];   // ffn intermediate

// ---------------------------------------------------------------------------
// Fused (optional add) + RMSNorm.  One block per row (D=1024), 256 threads,
// one float4 per thread.
// ---------------------------------------------------------------------------
template <bool ADD>
__global__ void rmsnorm_kernel(const float* __restrict__ A,
                               const float* __restrict__ Bp,
                               const float* __restrict__ g,
                               float* __restrict__ x_out,
                               float* __restrict__ h_out)
{
    int row = blockIdx.x;
    int t   = threadIdx.x;
    long base = (long)row * D_;

    float4 x = ((const float4*)(A + base))[t];
    if (ADD) {
        float4 b = ((const float4*)(Bp + base))[t];
        x.x += b.x; x.y += b.y; x.z += b.z; x.w += b.w;
    }
    float ss = x.x * x.x + x.y * x.y + x.z * x.z + x.w * x.w;
    #pragma unroll
    for (int off = 16; off > 0; off >>= 1)
        ss += __shfl_xor_sync(0xffffffffu, ss, off);

    __shared__ float sw[8];
    if ((t & 31) == 0) sw[t >> 5] = ss;
    __syncthreads();
    float tot = sw[0] + sw[1] + sw[2] + sw[3] + sw[4] + sw[5] + sw[6] + sw[7];
    float r = rsqrtf(tot * (1.0f / (float)D_) + 1e-6f);

    float4 gg = ((const float4*)g)[t];
    float4 h;
    h.x = x.x * r * gg.x;  h.y = x.y * r * gg.y;
    h.z = x.z * r * gg.z;  h.w = x.w * r * gg.w;

    if (ADD) ((float4*)(x_out + base))[t] = x;   // keep residual x
    ((float4*)(h_out + base))[t] = h;
}

// ---------------------------------------------------------------------------
// SGEMM: C[M,N] = epilogue( A[M,K] * B[N,K]^T ),  all row-major.
// 128x128 block tile, BK=8, 256 threads, 8x8 per-thread micro-tile,
// double-buffered shared memory.  M,N multiples of 128; K multiple of 8.
// EPI: 0 = none, 1 = SiLU, 2 = residual add (C = R + acc).
// ---------------------------------------------------------------------------
#define EPI_NONE 0
#define EPI_SILU 1
#define EPI_RES  2

template <int EPI>
__global__ void __launch_bounds__(256) sgemm_kernel(
    const float* __restrict__ A, const float* __restrict__ B,
    const float* __restrict__ R, float* __restrict__ C,
    int M, int N, int K)
{
    __shared__ float As[2][8][132];
    __shared__ float Bs[2][8][132];

    int t  = threadIdx.x;
    int tx = t & 15, ty = t >> 4;
    int bm = blockIdx.y << 7;
    int bn = blockIdx.x << 7;

    int lr = t >> 1;          // 0..127 tile row for loading
    int lc = (t & 1) << 2;    // 0 or 4 k-offset

    const float* Ap = A + (long)(bm + lr) * K + lc;
    const float* Bp = B + (long)(bn + lr) * K + lc;

    float acc[8][8];
    #pragma unroll
    for (int i = 0; i < 8; ++i)
        #pragma unroll
        for (int j = 0; j < 8; ++j) acc[i][j] = 0.0f;

    // prologue: tile 0
    {
        float4 av = *(const float4*)Ap;
        float4 bv = *(const float4*)Bp;
        As[0][lc + 0][lr] = av.x; As[0][lc + 1][lr] = av.y;
        As[0][lc + 2][lr] = av.z; As[0][lc + 3][lr] = av.w;
        Bs[0][lc + 0][lr] = bv.x; Bs[0][lc + 1][lr] = bv.y;
        Bs[0][lc + 2][lr] = bv.z; Bs[0][lc + 3][lr] = bv.w;
    }
    __syncthreads();

    int nt  = K >> 3;
    int buf = 0;
    for (int ts = 0; ts < nt; ++ts) {
        float4 a2, b2;
        bool more = (ts < nt - 1);
        if (more) {
            a2 = *(const float4*)(Ap + (ts + 1) * 8);
            b2 = *(const float4*)(Bp + (ts + 1) * 8);
        }
        #pragma unroll
        for (int k = 0; k < 8; ++k) {
            float a[8], b[8];
            *(float4*)(a)     = *(const float4*)&As[buf][k][ty * 8];
            *(float4*)(a + 4) = *(const float4*)&As[buf][k][ty * 8 + 4];
            *(float4*)(b)     = *(const float4*)&Bs[buf][k][tx * 8];
            *(float4*)(b + 4) = *(const float4*)&Bs[buf][k][tx * 8 + 4];
            #pragma unroll
            for (int i = 0; i < 8; ++i)
                #pragma unroll
                for (int j = 0; j < 8; ++j)
                    acc[i][j] += a[i] * b[j];
        }
        if (more) {
            int nb = buf ^ 1;
            As[nb][lc + 0][lr] = a2.x; As[nb][lc + 1][lr] = a2.y;
            As[nb][lc + 2][lr] = a2.z; As[nb][lc + 3][lr] = a2.w;
            Bs[nb][lc + 0][lr] = b2.x; Bs[nb][lc + 1][lr] = b2.y;
            Bs[nb][lc + 2][lr] = b2.z; Bs[nb][lc + 3][lr] = b2.w;
        }
        __syncthreads();
        buf ^= 1;
    }

    // epilogue
    #pragma unroll
    for (int i = 0; i < 8; ++i) {
        long row = bm + ty * 8 + i;
        long off = row * (long)N + bn + tx * 8;
        #pragma unroll
        for (int jj = 0; jj < 2; ++jj) {
            float4 v;
            v.x = acc[i][jj * 4 + 0]; v.y = acc[i][jj * 4 + 1];
            v.z = acc[i][jj * 4 + 2]; v.w = acc[i][jj * 4 + 3];
            if (EPI == EPI_SILU) {
                v.x = v.x / (1.0f + __expf(-v.x));
                v.y = v.y / (1.0f + __expf(-v.y));
                v.z = v.z / (1.0f + __expf(-v.z));
                v.w = v.w / (1.0f + __expf(-v.w));
            } else if (EPI == EPI_RES) {
                float4 rr = *(const float4*)(R + off + jj * 4);
                v.x += rr.x; v.y += rr.y; v.z += rr.z; v.w += rr.w;
            }
            *(float4*)(C + off + jj * 4) = v;
        }
    }
}

// ---------------------------------------------------------------------------
// RoPE applied in place to q and k segments of g_qkv.
// idx bits: j[0:5) head-dim-half, h[5:9), s[9:10) (q/k), l[10:21), b[21:22)
// inv_freq computed in double to match the fp32 reference to < 1 ulp,
// accurate sincosf (phases up to ~2047 rad).
// ---------------------------------------------------------------------------
__global__ void rope_kernel(float* __restrict__ qkv)
{
    int idx = blockIdx.x * blockDim.x + threadIdx.x;  // 2^22 threads total
    int j  = idx & 31;
    int hh = (idx >> 5) & 15;
    int s  = (idx >> 9) & 1;
    int l  = (idx >> 10) & 2047;
    int b  = idx >> 21;

    // 1 / 10000^(j/32), computed in double, rounded to fp32
    double dinv = exp(-(double)j * (9.210340371976184 / 32.0));
    float  invf = (float)dinv;
    float  fr   = (float)l * invf;
    float sn, cs;
    sincosf(fr, &sn, &cs);

    long base = (long)(b * L_ + l) * D3 + s * D_ + hh * HD_ + j;
    float x1 = qkv[base];
    float x2 = qkv[base + 32];
    qkv[base]      = x1 * cs - x2 * sn;
    qkv[base + 32] = x2 * cs + x1 * sn;
}

// ---------------------------------------------------------------------------
// Flash attention, fp32.  One block per (q-tile of 128, head, batch).
// 256 threads = 16x16 grid: rows r = ty*8..ty*8+7, score cols k = tx + 16*j,
// output cols d = tx*4..tx*4+3.  Bc = 64, 32 K-tiles.  Q pre-scaled by 1/8.
// Dynamic smem: Qs[128][68] Ks[64][68] Vs[64][68] Ps[128][68] = 102 KB.
// ---------------------------------------------------------------------------
#define FLASH_SMEM (384 * 68 * 4)

__global__ void __launch_bounds__(256) flash_kernel(
    const float* __restrict__ qkv, float* __restrict__ out)
{
    extern __shared__ float sm[];
    float (*Qs)[68] = (float(*)[68])(sm);
    float (*Ks)[68] = (float(*)[68])(sm + 128 * 68);
    float (*Vs)[68] = (float(*)[68])(sm + 192 * 68);
    float (*Ps)[68] = (float(*)[68])(sm + 256 * 68);

    int t  = threadIdx.x;
    int tx = t & 15, ty = t >> 4;
    int q0 = blockIdx.x << 7;
    int h  = blockIdx.y;
    int b  = blockIdx.z;

    const float* base = qkv + (long)b * L_ * D3 + h * HD_;

    // load + pre-scale Q tile (128 x 64)
    for (int i = t; i < 128 * 16; i += 256) {
        int r = i >> 4, c4 = (i & 15) << 2;
        float4 v = *(const float4*)(base + (long)(q0 + r) * D3 + c4);
        v.x *= 0.125f; v.y *= 0.125f; v.z *= 0.125f; v.w *= 0.125f;
        *(float4*)&Qs[r][c4] = v;
    }

    float m[8], l[8], o[8][4];
    #pragma unroll
    for (int i = 0; i < 8; ++i) {
        m[i] = -1e30f; l[i] = 0.0f;
        o[i][0] = o[i][1] = o[i][2] = o[i][3] = 0.0f;
    }
    __syncthreads();

    for (int kt = 0; kt < 32; ++kt) {
        int k0 = kt << 6;
        // load K, V tiles (64 x 64 each)
        for (int i = t; i < 64 * 16; i += 256) {
            int r = i >> 4, c4 = (i & 15) << 2;
            *(float4*)&Ks[r][c4] =
                *(const float4*)(base + D_     + (long)(k0 + r) * D3 + c4);
            *(float4*)&Vs[r][c4] =
                *(const float4*)(base + 2 * D_ + (long)(k0 + r) * D3 + c4);
        }
        __syncthreads();

        // S = Q * K^T (scaled)
        float s[8][4];
        #pragma unroll
        for (int i = 0; i < 8; ++i)
            s[i][0] = s[i][1] = s[i][2] = s[i][3] = 0.0f;

        #pragma unroll 4
        for (int d4 = 0; d4 < 64; d4 += 4) {
            float4 k0f = *(const float4*)&Ks[tx     ][d4];
            float4 k1f = *(const float4*)&Ks[tx + 16][d4];
            float4 k2f = *(const float4*)&Ks[tx + 32][d4];
            float4 k3f = *(const float4*)&Ks[tx + 48][d4];
            #pragma unroll
            for (int i = 0; i < 8; ++i) {
                float4 qf = *(const float4*)&Qs[ty * 8 + i][d4];
                s[i][0] += qf.x * k0f.x + qf.y * k0f.y + qf.z * k0f.z + qf.w * k0f.w;
                s[i][1] += qf.x * k1f.x + qf.y * k1f.y + qf.z * k1f.z + qf.w * k1f.w;
                s[i][2] += qf.x * k2f.x + qf.y * k2f.y + qf.z * k2f.z + qf.w * k2f.w;
                s[i][3] += qf.x * k3f.x + qf.y * k3f.y + qf.z * k3f.z + qf.w * k3f.w;
            }
        }

        // online softmax update + stage P to smem
        #pragma unroll
        for (int i = 0; i < 8; ++i) {
            float mx = fmaxf(fmaxf(s[i][0], s[i][1]), fmaxf(s[i][2], s[i][3]));
            #pragma unroll
            for (int off = 8; off > 0; off >>= 1)
                mx = fmaxf(mx, __shfl_xor_sync(0xffffffffu, mx, off));
            float mn    = fmaxf(m[i], mx);
            float alpha = __expf(m[i] - mn);
            m[i] = mn;
            float p0 = __expf(s[i][0] - mn), p1 = __expf(s[i][1] - mn);
            float p2 = __expf(s[i][2] - mn), p3 = __expf(s[i][3] - mn);
            float sum = p0 + p1 + p2 + p3;
            #pragma unroll
            for (int off = 8; off > 0; off >>= 1)
                sum += __shfl_xor_sync(0xffffffffu, sum, off);
            l[i] = l[i] * alpha + sum;
            o[i][0] *= alpha; o[i][1] *= alpha; o[i][2] *= alpha; o[i][3] *= alpha;
            int r = ty * 8 + i;
            Ps[r][tx] = p0; Ps[r][tx + 16] = p1; Ps[r][tx + 32] = p2; Ps[r][tx + 48] = p3;
        }
        __syncthreads();

        // O += P * V
        #pragma unroll 8
        for (int k = 0; k < 64; ++k) {
            float4 vv = *(const float4*)&Vs[k][tx << 2];
            #pragma unroll
            for (int i = 0; i < 8; ++i) {
                float p = Ps[ty * 8 + i][k];
                o[i][0] += p * vv.x; o[i][1] += p * vv.y;
                o[i][2] += p * vv.z; o[i][3] += p * vv.w;
            }
        }
        __syncthreads();
    }

    // write O / l to (b, l, h, d) laid out as [4096, 1024]
    #pragma unroll
    for (int i = 0; i < 8; ++i) {
        float inv = 1.0f / l[i];
        float4 v;
        v.x = o[i][0] * inv; v.y = o[i][1] * inv;
        v.z = o[i][2] * inv; v.w = o[i][3] * inv;
        long row = (long)b * L_ + q0 + ty * 8 + i;
        *(float4*)(out + row * D_ + h * HD_ + (tx << 2)) = v;
    }
}

// ---------------------------------------------------------------------------
// kernel_launch: the whole block as a kernel sequence on the default stream.
// ---------------------------------------------------------------------------
extern "C" void kernel_launch(void* const* d_in, const int* in_sizes, int n_in,
                              void* d_out, int out_size)
{
    const float* zH     = (const float*)d_in[0];
    const float* zL     = (const float*)d_in[1];
    const float* w_qkv  = (const float*)d_in[2];
    const float* w_out  = (const float*)d_in[3];
    const float* w_ffn1 = (const float*)d_in[4];
    const float* w_ffn2 = (const float*)d_in[5];
    const float* g1     = (const float*)d_in[6];
    const float* g2     = (const float*)d_in[7];
    float* out = (float*)d_out;

    float *px, *ph, *pqkv, *pao, *pmid;
    cudaGetSymbolAddress((void**)&px,   g_x);
    cudaGetSymbolAddress((void**)&ph,   g_h);
    cudaGetSymbolAddress((void**)&pqkv, g_qkv);
    cudaGetSymbolAddress((void**)&pao,  g_ao);
    cudaGetSymbolAddress((void**)&pmid, g_mid);

    cudaFuncSetAttribute(flash_kernel,
                         cudaFuncAttributeMaxDynamicSharedMemorySize,
                         FLASH_SMEM);

    // 1. x = zH + zL ; h = rmsnorm(x) * g1
    rmsnorm_kernel<true><<<ROWS, 256>>>(zH, zL, g1, px, ph);

    // 2. qkv = h @ w_qkv^T            [4096, 3072]
    sgemm_kernel<EPI_NONE><<<dim3(D3 / 128, ROWS / 128), 256>>>(
        ph, w_qkv, nullptr, pqkv, ROWS, D3, D_);

    // 3. RoPE on q, k (in place)
    rope_kernel<<<(B_ * L_ * 2 * H_ * 32) / 256, 256>>>(pqkv);

    // 4. attention -> g_ao            [4096, 1024]
    flash_kernel<<<dim3(L_ / 128, H_, B_), 256, FLASH_SMEM>>>(pqkv, pao);

    // 5. x2 = x + ao @ w_out^T        (in place into g_x)
    sgemm_kernel<EPI_RES><<<dim3(D_ / 128, ROWS / 128), 256>>>(
        pao, w_out, px, px, ROWS, D_, D_);

    // 6. h2 = rmsnorm(x2) * g2
    rmsnorm_kernel<false><<<ROWS, 256>>>(px, nullptr, g2, nullptr, ph);

    // 7. mid = silu(h2 @ w_ffn1^T)    [4096, 4096]
    sgemm_kernel<EPI_SILU><<<dim3(D4 / 128, ROWS / 128), 256>>>(
        ph, w_ffn1, nullptr, pmid, ROWS, D4, D_);

    // 8. out = x2 + mid @ w_ffn2^T    [4096, 1024]
    sgemm_kernel<EPI_RES><<<dim3(D_ / 128, ROWS / 128), 256>>>(
        pmid, w_ffn2, px, out, ROWS, D_, D4);
}

// round 11
// speedup vs baseline: 1.5234x; 1.5234x over previous
#include <cuda_runtime.h>
#include <cuda_bf16.h>
#include <math.h>
#include <cstdint>

// Problem constants
#define B_   2
#define L_   2048
#define D_   1024
#define H_   16
#define HD_  64
#define ROWS (B_ * L_)          // 4096
#define D3   (3 * D_)           // 3072
#define D4   (4 * D_)           // 4096

// ---------------------------------------------------------------------------
// Scratch (static __device__ arrays — no allocation allowed)
// ---------------------------------------------------------------------------
__device__ float g_x  [ROWS * D_];
__device__ float g_h  [ROWS * D_];
__device__ float g_qkv[ROWS * D3];
__device__ float g_ao [ROWS * D_];
__device__ float g_mid[ROWS * D4];

// ---------------------------------------------------------------------------
// PTX helpers (baseline ISA only — NO tcgen05, target is compute_103)
// ---------------------------------------------------------------------------
__device__ __forceinline__ uint32_t smem_u32(const void* p) {
    uint32_t a;
    asm("{ .reg .u64 t; cvta.to.shared.u64 t, %1; cvt.u32.u64 %0, t; }"
        : "=r"(a) : "l"(p));
    return a;
}

#define LDSM_X4(R0, R1, R2, R3, ADDR)                                         \
    asm volatile("ldmatrix.sync.aligned.m8n8.x4.shared.b16 {%0,%1,%2,%3}, [%4];" \
                 : "=r"(R0), "=r"(R1), "=r"(R2), "=r"(R3) : "r"(ADDR))

#define MMA_BF16(c, a, b)                                                     \
    asm volatile("mma.sync.aligned.m16n8k16.row.col.f32.bf16.bf16.f32 "       \
                 "{%0,%1,%2,%3}, {%4,%5,%6,%7}, {%8,%9}, {%0,%1,%2,%3};"      \
                 : "+f"((c)[0]), "+f"((c)[1]), "+f"((c)[2]), "+f"((c)[3])     \
                 : "r"((a)[0]), "r"((a)[1]), "r"((a)[2]), "r"((a)[3]),        \
                   "r"((b)[0]), "r"((b)[1]))

// ---------------------------------------------------------------------------
// Fused (optional add) + RMSNorm.
// ---------------------------------------------------------------------------
template <bool ADD>
__global__ void rmsnorm_kernel(const float* __restrict__ A,
                               const float* __restrict__ Bp,
                               const float* __restrict__ g,
                               float* __restrict__ x_out,
                               float* __restrict__ h_out)
{
    int row = blockIdx.x;
    int t   = threadIdx.x;
    long base = (long)row * D_;

    float4 x = ((const float4*)(A + base))[t];
    if (ADD) {
        float4 b = ((const float4*)(Bp + base))[t];
        x.x += b.x; x.y += b.y; x.z += b.z; x.w += b.w;
    }
    float ss = x.x * x.x + x.y * x.y + x.z * x.z + x.w * x.w;
    #pragma unroll
    for (int off = 16; off > 0; off >>= 1)
        ss += __shfl_xor_sync(0xffffffffu, ss, off);

    __shared__ float sw[8];
    if ((t & 31) == 0) sw[t >> 5] = ss;
    __syncthreads();
    float tot = sw[0] + sw[1] + sw[2] + sw[3] + sw[4] + sw[5] + sw[6] + sw[7];
    float r = rsqrtf(tot * (1.0f / (float)D_) + 1e-6f);

    float4 gg = ((const float4*)g)[t];
    float4 h;
    h.x = x.x * r * gg.x;  h.y = x.y * r * gg.y;
    h.z = x.z * r * gg.z;  h.w = x.w * r * gg.w;

    if (ADD) ((float4*)(x_out + base))[t] = x;
    ((float4*)(h_out + base))[t] = h;
}

// ---------------------------------------------------------------------------
// bf16-split tensor-core GEMM via mma.sync:
//   C[M,N] = epi( A[M,K] * B[N,K]^T ),  fp32 in/out.
// fp32 operand -> bf16 hi + bf16 lo; accumulate AhBh + AlBh + AhBl in fp32.
// CTA tile 128x128, K-chunk 32 fp32 cols, 8 warps (2M x 4N), warp tile 64x32.
//
// SMEM layout per tile: 128 rows x 64 bytes (32 bf16).  Swizzle at 16-byte
// granularity: unit u in [0,4) holds bf16 cols u*8..u*8+7, stored at
//   byte = row*64 + (u ^ (row&3))*16 (+8 for the odd half when storing f4).
// ldmatrix always addresses even 8-byte units -> 16B aligned.
// ---------------------------------------------------------------------------
#define EPI_NONE 0
#define EPI_SILU 1
#define EPI_RES  2

// c8 = 8-byte unit index (0..7); 16B unit = c8>>1, half = c8&1.
__device__ __forceinline__ uint32_t swz_off(int row, int c8) {
    return (uint32_t)(row * 64 + ((((c8 >> 1) ^ (row & 3)) << 4)) + ((c8 & 1) << 3));
}

__device__ __forceinline__ uint32_t pack_bf2(__nv_bfloat16 a, __nv_bfloat16 b) {
    return (uint32_t)__bfloat16_as_ushort(a) |
           ((uint32_t)__bfloat16_as_ushort(b) << 16);
}

__device__ __forceinline__ void split_store(char* hb, char* lb,
                                            int r, int c8, float4 v)
{
    uint32_t off = swz_off(r, c8);
    __nv_bfloat16 h0 = __float2bfloat16(v.x), h1 = __float2bfloat16(v.y);
    __nv_bfloat16 h2 = __float2bfloat16(v.z), h3 = __float2bfloat16(v.w);
    uint2 hv;
    hv.x = pack_bf2(h0, h1);
    hv.y = pack_bf2(h2, h3);
    __nv_bfloat16 l0 = __float2bfloat16(v.x - __bfloat162float(h0));
    __nv_bfloat16 l1 = __float2bfloat16(v.y - __bfloat162float(h1));
    __nv_bfloat16 l2 = __float2bfloat16(v.z - __bfloat162float(h2));
    __nv_bfloat16 l3 = __float2bfloat16(v.w - __bfloat162float(h3));
    uint2 lv;
    lv.x = pack_bf2(l0, l1);
    lv.y = pack_bf2(l2, l3);
    *(uint2*)(hb + off) = hv;
    *(uint2*)(lb + off) = lv;
}

template <int EPI>
__global__ void __launch_bounds__(256) gemm_mma(
    const float* __restrict__ A, const float* __restrict__ B,
    const float* __restrict__ R, float* __restrict__ C,
    int M, int N, int K)
{
    __shared__ __align__(16) char sAh[8192], sAl[8192], sBh[8192], sBl[8192];

    int t   = threadIdx.x;
    int ln  = t & 31;
    int wid = t >> 5;
    int wm  = wid >> 2;      // 0..1  (M)
    int wn  = wid & 3;       // 0..3  (N)
    int bm  = blockIdx.y << 7;
    int bn  = blockIdx.x << 7;

    uint32_t uAh = smem_u32(sAh), uAl = smem_u32(sAl);
    uint32_t uBh = smem_u32(sBh), uBl = smem_u32(sBl);

    float acc[4][4][4];
    #pragma unroll
    for (int i = 0; i < 4; ++i)
        #pragma unroll
        for (int j = 0; j < 4; ++j)
            acc[i][j][0] = acc[i][j][1] = acc[i][j][2] = acc[i][j][3] = 0.0f;

    // loader geometry: 1024 float4 per tile, 4 per thread
    int lr[4], lc[4];
    #pragma unroll
    for (int i = 0; i < 4; ++i) {
        int idx = t + i * 256;
        lr[i] = idx >> 3;
        lc[i] = idx & 7;
    }

    const float* Ab = A + (long)bm * K;
    const float* Bb = B + (long)bn * K;

    // chunk 0
    #pragma unroll
    for (int i = 0; i < 4; ++i) {
        float4 va = *(const float4*)(Ab + (long)lr[i] * K + lc[i] * 4);
        split_store(sAh, sAl, lr[i], lc[i], va);
        float4 vb = *(const float4*)(Bb + (long)lr[i] * K + lc[i] * 4);
        split_store(sBh, sBl, lr[i], lc[i], vb);
    }
    __syncthreads();

    // ldmatrix lane geometry
    int a_row = ln & 15;
    int a_k8  = ln >> 4;                       // 0/1 (k8 half)
    int gq    = ln >> 3;
    int b_row = ((gq >> 1) << 3) + (ln & 7);
    int b_k8  = gq & 1;

    int nc = K >> 5;
    float4 pa[4], pb[4];
    for (int c = 0; c < nc; ++c) {
        bool more = (c + 1 < nc);
        if (more) {
            #pragma unroll
            for (int i = 0; i < 4; ++i) {
                pa[i] = *(const float4*)(Ab + (long)lr[i] * K + (c + 1) * 32 + lc[i] * 4);
                pb[i] = *(const float4*)(Bb + (long)lr[i] * K + (c + 1) * 32 + lc[i] * 4);
            }
        }

        #pragma unroll
        for (int kh = 0; kh < 2; ++kh) {       // two k16 steps per chunk
            uint32_t ah[4][4], al[4][4], bh[4][2], bl[4][2];

            // 16B unit for this fragment half = kh*2 + k8  ->  c8 = unit*2
            #pragma unroll
            for (int mt = 0; mt < 4; ++mt) {
                int row = wm * 64 + mt * 16 + a_row;
                uint32_t off = swz_off(row, (kh * 2 + a_k8) * 2);
                LDSM_X4(ah[mt][0], ah[mt][1], ah[mt][2], ah[mt][3], uAh + off);
                LDSM_X4(al[mt][0], al[mt][1], al[mt][2], al[mt][3], uAl + off);
            }
            #pragma unroll
            for (int np = 0; np < 2; ++np) {   // n-tile pairs {0,1},{2,3}
                int row = wn * 32 + np * 16 + b_row;
                uint32_t off = swz_off(row, (kh * 2 + b_k8) * 2);
                uint32_t r0, r1, r2, r3;
                LDSM_X4(r0, r1, r2, r3, uBh + off);
                bh[np * 2][0] = r0; bh[np * 2][1] = r1;
                bh[np * 2 + 1][0] = r2; bh[np * 2 + 1][1] = r3;
                LDSM_X4(r0, r1, r2, r3, uBl + off);
                bl[np * 2][0] = r0; bl[np * 2][1] = r1;
                bl[np * 2 + 1][0] = r2; bl[np * 2 + 1][1] = r3;
            }

            #pragma unroll
            for (int mt = 0; mt < 4; ++mt)
                #pragma unroll
                for (int nt = 0; nt < 4; ++nt)
                    MMA_BF16(acc[mt][nt], ah[mt], bh[nt]);
            #pragma unroll
            for (int mt = 0; mt < 4; ++mt)
                #pragma unroll
                for (int nt = 0; nt < 4; ++nt)
                    MMA_BF16(acc[mt][nt], al[mt], bh[nt]);
            #pragma unroll
            for (int mt = 0; mt < 4; ++mt)
                #pragma unroll
                for (int nt = 0; nt < 4; ++nt)
                    MMA_BF16(acc[mt][nt], ah[mt], bl[nt]);
        }
        __syncthreads();
        if (more) {
            #pragma unroll
            for (int i = 0; i < 4; ++i) {
                split_store(sAh, sAl, lr[i], lc[i], pa[i]);
                split_store(sBh, sBl, lr[i], lc[i], pb[i]);
            }
        }
        __syncthreads();
    }

    // epilogue
    int er = ln >> 2;
    int ec = (ln & 3) << 1;
    #pragma unroll
    for (int mt = 0; mt < 4; ++mt) {
        #pragma unroll
        for (int nt = 0; nt < 4; ++nt) {
            long row0 = bm + wm * 64 + mt * 16 + er;
            long col  = bn + wn * 32 + nt * 8 + ec;
            #pragma unroll
            for (int hrow = 0; hrow < 2; ++hrow) {
                long off = (row0 + hrow * 8) * (long)N + col;
                float2 v;
                v.x = acc[mt][nt][hrow * 2 + 0];
                v.y = acc[mt][nt][hrow * 2 + 1];
                if (EPI == EPI_SILU) {
                    v.x = v.x / (1.0f + __expf(-v.x));
                    v.y = v.y / (1.0f + __expf(-v.y));
                } else if (EPI == EPI_RES) {
                    float2 rr = *(const float2*)(R + off);
                    v.x += rr.x; v.y += rr.y;
                }
                *(float2*)(C + off) = v;
            }
        }
    }
}

// ---------------------------------------------------------------------------
// RoPE applied in place to q and k segments of g_qkv.
// ---------------------------------------------------------------------------
__global__ void rope_kernel(float* __restrict__ qkv)
{
    int idx = blockIdx.x * blockDim.x + threadIdx.x;
    int j  = idx & 31;
    int hh = (idx >> 5) & 15;
    int s  = (idx >> 9) & 1;
    int l  = (idx >> 10) & 2047;
    int b  = idx >> 21;

    double dinv = exp(-(double)j * (9.210340371976184 / 32.0));
    float  invf = (float)dinv;
    float  fr   = (float)l * invf;
    float sn, cs;
    sincosf(fr, &sn, &cs);

    long base = (long)(b * L_ + l) * D3 + s * D_ + hh * HD_ + j;
    float x1 = qkv[base];
    float x2 = qkv[base + 32];
    qkv[base]      = x1 * cs - x2 * sn;
    qkv[base + 32] = x2 * cs + x1 * sn;
}

// ---------------------------------------------------------------------------
// Flash attention, fp32 (unchanged, known-good: 962us)
// ---------------------------------------------------------------------------
#define FLASH_SMEM (384 * 68 * 4)

__global__ void __launch_bounds__(256) flash_kernel(
    const float* __restrict__ qkv, float* __restrict__ out)
{
    extern __shared__ float sm[];
    float (*Qs)[68] = (float(*)[68])(sm);
    float (*Ks)[68] = (float(*)[68])(sm + 128 * 68);
    float (*Vs)[68] = (float(*)[68])(sm + 192 * 68);
    float (*Ps)[68] = (float(*)[68])(sm + 256 * 68);

    int t  = threadIdx.x;
    int tx = t & 15, ty = t >> 4;
    int q0 = blockIdx.x << 7;
    int h  = blockIdx.y;
    int b  = blockIdx.z;

    const float* base = qkv + (long)b * L_ * D3 + h * HD_;

    for (int i = t; i < 128 * 16; i += 256) {
        int r = i >> 4, c4 = (i & 15) << 2;
        float4 v = *(const float4*)(base + (long)(q0 + r) * D3 + c4);
        v.x *= 0.125f; v.y *= 0.125f; v.z *= 0.125f; v.w *= 0.125f;
        *(float4*)&Qs[r][c4] = v;
    }

    float m[8], l[8], o[8][4];
    #pragma unroll
    for (int i = 0; i < 8; ++i) {
        m[i] = -1e30f; l[i] = 0.0f;
        o[i][0] = o[i][1] = o[i][2] = o[i][3] = 0.0f;
    }
    __syncthreads();

    for (int kt = 0; kt < 32; ++kt) {
        int k0 = kt << 6;
        for (int i = t; i < 64 * 16; i += 256) {
            int r = i >> 4, c4 = (i & 15) << 2;
            *(float4*)&Ks[r][c4] =
                *(const float4*)(base + D_     + (long)(k0 + r) * D3 + c4);
            *(float4*)&Vs[r][c4] =
                *(const float4*)(base + 2 * D_ + (long)(k0 + r) * D3 + c4);
        }
        __syncthreads();

        float s[8][4];
        #pragma unroll
        for (int i = 0; i < 8; ++i)
            s[i][0] = s[i][1] = s[i][2] = s[i][3] = 0.0f;

        #pragma unroll 4
        for (int d4 = 0; d4 < 64; d4 += 4) {
            float4 k0f = *(const float4*)&Ks[tx     ][d4];
            float4 k1f = *(const float4*)&Ks[tx + 16][d4];
            float4 k2f = *(const float4*)&Ks[tx + 32][d4];
            float4 k3f = *(const float4*)&Ks[tx + 48][d4];
            #pragma unroll
            for (int i = 0; i < 8; ++i) {
                float4 qf = *(const float4*)&Qs[ty * 8 + i][d4];
                s[i][0] += qf.x * k0f.x + qf.y * k0f.y + qf.z * k0f.z + qf.w * k0f.w;
                s[i][1] += qf.x * k1f.x + qf.y * k1f.y + qf.z * k1f.z + qf.w * k1f.w;
                s[i][2] += qf.x * k2f.x + qf.y * k2f.y + qf.z * k2f.z + qf.w * k2f.w;
                s[i][3] += qf.x * k3f.x + qf.y * k3f.y + qf.z * k3f.z + qf.w * k3f.w;
            }
        }

        #pragma unroll
        for (int i = 0; i < 8; ++i) {
            float mx = fmaxf(fmaxf(s[i][0], s[i][1]), fmaxf(s[i][2], s[i][3]));
            #pragma unroll
            for (int off = 8; off > 0; off >>= 1)
                mx = fmaxf(mx, __shfl_xor_sync(0xffffffffu, mx, off));
            float mn    = fmaxf(m[i], mx);
            float alpha = __expf(m[i] - mn);
            m[i] = mn;
            float p0 = __expf(s[i][0] - mn), p1 = __expf(s[i][1] - mn);
            float p2 = __expf(s[i][2] - mn), p3 = __expf(s[i][3] - mn);
            float sum = p0 + p1 + p2 + p3;
            #pragma unroll
            for (int off = 8; off > 0; off >>= 1)
                sum += __shfl_xor_sync(0xffffffffu, sum, off);
            l[i] = l[i] * alpha + sum;
            o[i][0] *= alpha; o[i][1] *= alpha; o[i][2] *= alpha; o[i][3] *= alpha;
            int r = ty * 8 + i;
            Ps[r][tx] = p0; Ps[r][tx + 16] = p1; Ps[r][tx + 32] = p2; Ps[r][tx + 48] = p3;
        }
        __syncthreads();

        #pragma unroll 8
        for (int k = 0; k < 64; ++k) {
            float4 vv = *(const float4*)&Vs[k][tx << 2];
            #pragma unroll
            for (int i = 0; i < 8; ++i) {
                float p = Ps[ty * 8 + i][k];
                o[i][0] += p * vv.x; o[i][1] += p * vv.y;
                o[i][2] += p * vv.z; o[i][3] += p * vv.w;
            }
        }
        __syncthreads();
    }

    #pragma unroll
    for (int i = 0; i < 8; ++i) {
        float inv = 1.0f / l[i];
        float4 v;
        v.x = o[i][0] * inv; v.y = o[i][1] * inv;
        v.z = o[i][2] * inv; v.w = o[i][3] * inv;
        long row = (long)b * L_ + q0 + ty * 8 + i;
        *(float4*)(out + row * D_ + h * HD_ + (tx << 2)) = v;
    }
}

// ---------------------------------------------------------------------------
// kernel_launch
// ---------------------------------------------------------------------------
extern "C" void kernel_launch(void* const* d_in, const int* in_sizes, int n_in,
                              void* d_out, int out_size)
{
    const float* zH     = (const float*)d_in[0];
    const float* zL     = (const float*)d_in[1];
    const float* w_qkv  = (const float*)d_in[2];
    const float* w_out  = (const float*)d_in[3];
    const float* w_ffn1 = (const float*)d_in[4];
    const float* w_ffn2 = (const float*)d_in[5];
    const float* g1     = (const float*)d_in[6];
    const float* g2     = (const float*)d_in[7];
    float* out = (float*)d_out;

    float *px, *ph, *pqkv, *pao, *pmid;
    cudaGetSymbolAddress((void**)&px,   g_x);
    cudaGetSymbolAddress((void**)&ph,   g_h);
    cudaGetSymbolAddress((void**)&pqkv, g_qkv);
    cudaGetSymbolAddress((void**)&pao,  g_ao);
    cudaGetSymbolAddress((void**)&pmid, g_mid);

    cudaFuncSetAttribute(flash_kernel,
                         cudaFuncAttributeMaxDynamicSharedMemorySize, FLASH_SMEM);

    // 1. x = zH + zL ; h = rmsnorm(x) * g1
    rmsnorm_kernel<true><<<ROWS, 256>>>(zH, zL, g1, px, ph);

    // 2. qkv = h @ w_qkv^T            [4096, 3072]
    gemm_mma<EPI_NONE><<<dim3(D3 / 128, ROWS / 128), 256>>>(
        ph, w_qkv, nullptr, pqkv, ROWS, D3, D_);

    // 3. RoPE on q, k (in place)
    rope_kernel<<<(B_ * L_ * 2 * H_ * 32) / 256, 256>>>(pqkv);

    // 4. attention -> g_ao            [4096, 1024]
    flash_kernel<<<dim3(L_ / 128, H_, B_), 256, FLASH_SMEM>>>(pqkv, pao);

    // 5. x2 = x + ao @ w_out^T        (in place into g_x)
    gemm_mma<EPI_RES><<<dim3(D_ / 128, ROWS / 128), 256>>>(
        pao, w_out, px, px, ROWS, D_, D_);

    // 6. h2 = rmsnorm(x2) * g2
    rmsnorm_kernel<false><<<ROWS, 256>>>(px, nullptr, g2, nullptr, ph);

    // 7. mid = silu(h2 @ w_ffn1^T)    [4096, 4096]
    gemm_mma<EPI_SILU><<<dim3(D4 / 128, ROWS / 128), 256>>>(
        ph, w_ffn1, nullptr, pmid, ROWS, D4, D_);

    // 8. out = x2 + mid @ w_ffn2^T    [4096, 1024]
    gemm_mma<EPI_RES><<<dim3(D_ / 128, ROWS / 128), 256>>>(
        pmid, w_ffn2, px, out, ROWS, D_, D4);
}

// round 12
// speedup vs baseline: 1.8988x; 1.2464x over previous
#include <cuda_runtime.h>
#include <cuda_bf16.h>
#include <math.h>
#include <cstdint>

// Problem constants
#define B_   2
#define L_   2048
#define D_   1024
#define H_   16
#define HD_  64
#define ROWS (B_ * L_)          // 4096
#define D3   (3 * D_)           // 3072
#define D4   (4 * D_)           // 4096

typedef unsigned short u16;

// ---------------------------------------------------------------------------
// Scratch (static __device__ arrays — no allocation allowed)
// ---------------------------------------------------------------------------
__device__ float g_x  [ROWS * D_];   // residual stream (fp32)
__device__ float g_qkv[ROWS * D3];   // qkv (fp32, consumed by rope/flash)

__device__ u16 g_h_hi [ROWS * D_],  g_h_lo [ROWS * D_];   // rmsnorm out (bf16 split)
__device__ u16 g_ao_hi[ROWS * D_],  g_ao_lo[ROWS * D_];   // attention out
__device__ u16 g_mid_hi[ROWS * D4], g_mid_lo[ROWS * D4];  // ffn intermediate

__device__ u16 g_w1_hi[D3 * D_], g_w1_lo[D3 * D_];        // w_qkv
__device__ u16 g_w2_hi[D_ * D_], g_w2_lo[D_ * D_];        // w_out
__device__ u16 g_w3_hi[D4 * D_], g_w3_lo[D4 * D_];        // w_ffn1
__device__ u16 g_w4_hi[D_ * D4], g_w4_lo[D_ * D4];        // w_ffn2

// ---------------------------------------------------------------------------
// PTX helpers (baseline ISA only — target is compute_103, no tcgen05)
// ---------------------------------------------------------------------------
__device__ __forceinline__ uint32_t smem_u32(const void* p) {
    uint32_t a;
    asm("{ .reg .u64 t; cvta.to.shared.u64 t, %1; cvt.u32.u64 %0, t; }"
        : "=r"(a) : "l"(p));
    return a;
}

#define LDSM_X4(R0, R1, R2, R3, ADDR)                                         \
    asm volatile("ldmatrix.sync.aligned.m8n8.x4.shared.b16 {%0,%1,%2,%3}, [%4];" \
                 : "=r"(R0), "=r"(R1), "=r"(R2), "=r"(R3) : "r"(ADDR))

#define MMA_BF16(c, a, b)                                                     \
    asm volatile("mma.sync.aligned.m16n8k16.row.col.f32.bf16.bf16.f32 "       \
                 "{%0,%1,%2,%3}, {%4,%5,%6,%7}, {%8,%9}, {%0,%1,%2,%3};"      \
                 : "+f"((c)[0]), "+f"((c)[1]), "+f"((c)[2]), "+f"((c)[3])     \
                 : "r"((a)[0]), "r"((a)[1]), "r"((a)[2]), "r"((a)[3]),        \
                   "r"((b)[0]), "r"((b)[1]))

#define CP16(s, g)  asm volatile("cp.async.cg.shared.global [%0], [%1], 16;" \
                                 :: "r"(s), "l"(g))
#define CP_COMMIT() asm volatile("cp.async.commit_group;")
#define CP_WAIT1()  asm volatile("cp.async.wait_group 1;")
#define CP_WAIT0()  asm volatile("cp.async.wait_group 0;")

// ---------------------------------------------------------------------------
// bf16 hi/lo split helpers
// ---------------------------------------------------------------------------
__device__ __forceinline__ uint32_t pack_bf2(__nv_bfloat16 a, __nv_bfloat16 b) {
    return (uint32_t)__bfloat16_as_ushort(a) |
           ((uint32_t)__bfloat16_as_ushort(b) << 16);
}

__device__ __forceinline__ void split4(float4 v, uint2& hv, uint2& lv) {
    __nv_bfloat16 h0 = __float2bfloat16(v.x), h1 = __float2bfloat16(v.y);
    __nv_bfloat16 h2 = __float2bfloat16(v.z), h3 = __float2bfloat16(v.w);
    hv.x = pack_bf2(h0, h1);
    hv.y = pack_bf2(h2, h3);
    __nv_bfloat16 l0 = __float2bfloat16(v.x - __bfloat162float(h0));
    __nv_bfloat16 l1 = __float2bfloat16(v.y - __bfloat162float(h1));
    __nv_bfloat16 l2 = __float2bfloat16(v.z - __bfloat162float(h2));
    __nv_bfloat16 l3 = __float2bfloat16(v.w - __bfloat162float(h3));
    lv.x = pack_bf2(l0, l1);
    lv.y = pack_bf2(l2, l3);
}

// weight split: fp32 -> bf16 hi/lo (4 elements per thread)
__global__ void splitw_kernel(const float* __restrict__ w,
                              u16* __restrict__ hi, u16* __restrict__ lo)
{
    long i = (long)blockIdx.x * blockDim.x + threadIdx.x;
    float4 v = ((const float4*)w)[i];
    uint2 hv, lv;
    split4(v, hv, lv);
    ((uint2*)hi)[i] = hv;
    ((uint2*)lo)[i] = lv;
}

// ---------------------------------------------------------------------------
// Fused (optional add) + RMSNorm -> bf16 split output.
// ---------------------------------------------------------------------------
template <bool ADD>
__global__ void rmsnorm_kernel(const float* __restrict__ A,
                               const float* __restrict__ Bp,
                               const float* __restrict__ g,
                               float* __restrict__ x_out,
                               u16* __restrict__ h_hi,
                               u16* __restrict__ h_lo)
{
    int row = blockIdx.x;
    int t   = threadIdx.x;
    long base = (long)row * D_;

    float4 x = ((const float4*)(A + base))[t];
    if (ADD) {
        float4 b = ((const float4*)(Bp + base))[t];
        x.x += b.x; x.y += b.y; x.z += b.z; x.w += b.w;
    }
    float ss = x.x * x.x + x.y * x.y + x.z * x.z + x.w * x.w;
    #pragma unroll
    for (int off = 16; off > 0; off >>= 1)
        ss += __shfl_xor_sync(0xffffffffu, ss, off);

    __shared__ float sw[8];
    if ((t & 31) == 0) sw[t >> 5] = ss;
    __syncthreads();
    float tot = sw[0] + sw[1] + sw[2] + sw[3] + sw[4] + sw[5] + sw[6] + sw[7];
    float r = rsqrtf(tot * (1.0f / (float)D_) + 1e-6f);

    float4 gg = ((const float4*)g)[t];
    float4 h;
    h.x = x.x * r * gg.x;  h.y = x.y * r * gg.y;
    h.z = x.z * r * gg.z;  h.w = x.w * r * gg.w;

    if (ADD) ((float4*)(x_out + base))[t] = x;
    uint2 hv, lv;
    split4(h, hv, lv);
    ((uint2*)h_hi)[row * 256 + t] = hv;
    ((uint2*)h_lo)[row * 256 + t] = lv;
}

// ---------------------------------------------------------------------------
// bf16-split tensor-core GEMM v2:  C = epi( A[M,K] * B[N,K]^T )
// Operands pre-split in gmem (bf16 hi/lo).  3 terms: AhBh + AlBh + AhBl.
// CTA 128x128, K-chunk 32, 8 warps (2M x 4N), warp tile 64x32.
// cp.async 3-stage pipeline; smem rows 64B; swizzle u ^= (row>>1)&3
// (conflict-free for ldmatrix m8n8 and cp.async stores).
// ---------------------------------------------------------------------------
#define EPI_NONE 0
#define EPI_SILU 1
#define EPI_RES  2

#define GEMM_STG   32768           // bytes per stage (4 tiles x 8KB)
#define GEMM_SMEM  (3 * GEMM_STG)  // 96KB

__device__ __forceinline__ uint32_t swz(int row, int u) {
    return (uint32_t)(row * 64 + ((u ^ ((row >> 1) & 3)) << 4));
}

template <int EPI>
__global__ void __launch_bounds__(256) gemm_bf3(
    const u16* __restrict__ Ah, const u16* __restrict__ Al,
    const u16* __restrict__ Bh, const u16* __restrict__ Bl,
    const float* __restrict__ R, float* __restrict__ C,
    u16* __restrict__ Chi, u16* __restrict__ Clo,
    int M, int N, int K)
{
    extern __shared__ char smx[];
    uint32_t sb = smem_u32(smx);

    int t   = threadIdx.x;
    int ln  = t & 31;
    int wid = t >> 5;
    int wm  = wid >> 2;
    int wn  = wid & 3;
    int bm  = blockIdx.y << 7;
    int bn  = blockIdx.x << 7;

    // loader: row = t>>1, units u = (t&1)*2 + {0,1}
    int lrow = t >> 1;
    int lu0  = (t & 1) << 1;
    const u16* gAh = Ah + (long)(bm + lrow) * K;
    const u16* gAl = Al + (long)(bm + lrow) * K;
    const u16* gBh = Bh + (long)(bn + lrow) * K;
    const u16* gBl = Bl + (long)(bn + lrow) * K;
    uint32_t so0 = swz(lrow, lu0);
    uint32_t so1 = swz(lrow, lu0 + 1);
    int go0 = lu0 * 8, go1 = lu0 * 8 + 8;

    float acc[4][4][4];
    #pragma unroll
    for (int i = 0; i < 4; ++i)
        #pragma unroll
        for (int j = 0; j < 4; ++j)
            acc[i][j][0] = acc[i][j][1] = acc[i][j][2] = acc[i][j][3] = 0.0f;

    int nc = K >> 5;

    // prologue: stages 0,1
    {
        uint32_t b0 = sb;
        CP16(b0 + so0,         gAh + go0);  CP16(b0 + so1,         gAh + go1);
        CP16(b0 + 8192 + so0,  gAl + go0);  CP16(b0 + 8192 + so1,  gAl + go1);
        CP16(b0 + 16384 + so0, gBh + go0);  CP16(b0 + 16384 + so1, gBh + go1);
        CP16(b0 + 24576 + so0, gBl + go0);  CP16(b0 + 24576 + so1, gBl + go1);
        CP_COMMIT();
        if (nc > 1) {
            uint32_t b1 = sb + GEMM_STG;
            CP16(b1 + so0,         gAh + 32 + go0);  CP16(b1 + so1,         gAh + 32 + go1);
            CP16(b1 + 8192 + so0,  gAl + 32 + go0);  CP16(b1 + 8192 + so1,  gAl + 32 + go1);
            CP16(b1 + 16384 + so0, gBh + 32 + go0);  CP16(b1 + 16384 + so1, gBh + 32 + go1);
            CP16(b1 + 24576 + so0, gBl + 32 + go0);  CP16(b1 + 24576 + so1, gBl + 32 + go1);
            CP_COMMIT();
        }
    }

    // ldmatrix lane geometry
    int a_row = ln & 15;
    int a_k8  = ln >> 4;
    int gq    = ln >> 3;
    int b_row = ((gq >> 1) << 3) + (ln & 7);
    int b_k8  = gq & 1;

    int stage = 0;
    for (int c = 0; c < nc; ++c) {
        if (c + 1 < nc) { CP_WAIT1(); } else { CP_WAIT0(); }
        __syncthreads();

        if (c + 2 < nc) {
            int ns = stage + 2; if (ns >= 3) ns -= 3;
            uint32_t nb = sb + ns * GEMM_STG;
            long ko = (long)(c + 2) * 32;
            CP16(nb + so0,         gAh + ko + go0);  CP16(nb + so1,         gAh + ko + go1);
            CP16(nb + 8192 + so0,  gAl + ko + go0);  CP16(nb + 8192 + so1,  gAl + ko + go1);
            CP16(nb + 16384 + so0, gBh + ko + go0);  CP16(nb + 16384 + so1, gBh + ko + go1);
            CP16(nb + 24576 + so0, gBl + ko + go0);  CP16(nb + 24576 + so1, gBl + ko + go1);
            CP_COMMIT();
        }

        uint32_t uAh = sb + stage * GEMM_STG;
        uint32_t uAl = uAh + 8192;
        uint32_t uBh = uAh + 16384;
        uint32_t uBl = uAh + 24576;

        #pragma unroll
        for (int kh = 0; kh < 2; ++kh) {
            uint32_t ah[4][4], al[4][4], bh[4][2], bl[4][2];

            #pragma unroll
            for (int mt = 0; mt < 4; ++mt) {
                int row = wm * 64 + mt * 16 + a_row;
                uint32_t off = swz(row, kh * 2 + a_k8);
                LDSM_X4(ah[mt][0], ah[mt][1], ah[mt][2], ah[mt][3], uAh + off);
                LDSM_X4(al[mt][0], al[mt][1], al[mt][2], al[mt][3], uAl + off);
            }
            #pragma unroll
            for (int np = 0; np < 2; ++np) {
                int row = wn * 32 + np * 16 + b_row;
                uint32_t off = swz(row, kh * 2 + b_k8);
                uint32_t r0, r1, r2, r3;
                LDSM_X4(r0, r1, r2, r3, uBh + off);
                bh[np * 2][0] = r0; bh[np * 2][1] = r1;
                bh[np * 2 + 1][0] = r2; bh[np * 2 + 1][1] = r3;
                LDSM_X4(r0, r1, r2, r3, uBl + off);
                bl[np * 2][0] = r0; bl[np * 2][1] = r1;
                bl[np * 2 + 1][0] = r2; bl[np * 2 + 1][1] = r3;
            }

            #pragma unroll
            for (int mt = 0; mt < 4; ++mt)
                #pragma unroll
                for (int nt = 0; nt < 4; ++nt)
                    MMA_BF16(acc[mt][nt], ah[mt], bh[nt]);
            #pragma unroll
            for (int mt = 0; mt < 4; ++mt)
                #pragma unroll
                for (int nt = 0; nt < 4; ++nt)
                    MMA_BF16(acc[mt][nt], al[mt], bh[nt]);
            #pragma unroll
            for (int mt = 0; mt < 4; ++mt)
                #pragma unroll
                for (int nt = 0; nt < 4; ++nt)
                    MMA_BF16(acc[mt][nt], ah[mt], bl[nt]);
        }

        ++stage; if (stage == 3) stage = 0;
    }

    // epilogue
    int er = ln >> 2;
    int ec = (ln & 3) << 1;
    #pragma unroll
    for (int mt = 0; mt < 4; ++mt) {
        #pragma unroll
        for (int nt = 0; nt < 4; ++nt) {
            long row0 = bm + wm * 64 + mt * 16 + er;
            long col  = bn + wn * 32 + nt * 8 + ec;
            #pragma unroll
            for (int hrow = 0; hrow < 2; ++hrow) {
                long off = (row0 + hrow * 8) * (long)N + col;
                float vx = acc[mt][nt][hrow * 2 + 0];
                float vy = acc[mt][nt][hrow * 2 + 1];
                if (EPI == EPI_SILU) {
                    vx = vx / (1.0f + __expf(-vx));
                    vy = vy / (1.0f + __expf(-vy));
                    __nv_bfloat16 hx = __float2bfloat16(vx);
                    __nv_bfloat16 hy = __float2bfloat16(vy);
                    *(uint32_t*)(Chi + off) = pack_bf2(hx, hy);
                    *(uint32_t*)(Clo + off) = pack_bf2(
                        __float2bfloat16(vx - __bfloat162float(hx)),
                        __float2bfloat16(vy - __bfloat162float(hy)));
                } else {
                    if (EPI == EPI_RES) {
                        float2 rr = *(const float2*)(R + off);
                        vx += rr.x; vy += rr.y;
                    }
                    float2 v; v.x = vx; v.y = vy;
                    *(float2*)(C + off) = v;
                }
            }
        }
    }
}

// ---------------------------------------------------------------------------
// RoPE applied in place to q and k segments of g_qkv.
// ---------------------------------------------------------------------------
__global__ void rope_kernel(float* __restrict__ qkv)
{
    int idx = blockIdx.x * blockDim.x + threadIdx.x;
    int j  = idx & 31;
    int hh = (idx >> 5) & 15;
    int s  = (idx >> 9) & 1;
    int l  = (idx >> 10) & 2047;
    int b  = idx >> 21;

    double dinv = exp(-(double)j * (9.210340371976184 / 32.0));
    float  invf = (float)dinv;
    float  fr   = (float)l * invf;
    float sn, cs;
    sincosf(fr, &sn, &cs);

    long base = (long)(b * L_ + l) * D3 + s * D_ + hh * HD_ + j;
    float x1 = qkv[base];
    float x2 = qkv[base + 32];
    qkv[base]      = x1 * cs - x2 * sn;
    qkv[base + 32] = x2 * cs + x1 * sn;
}

// ---------------------------------------------------------------------------
// Flash attention, fp32 (epilogue now writes bf16 hi/lo for the out-proj GEMM)
// ---------------------------------------------------------------------------
#define FLASH_SMEM (384 * 68 * 4)

__global__ void __launch_bounds__(256) flash_kernel(
    const float* __restrict__ qkv,
    u16* __restrict__ out_hi, u16* __restrict__ out_lo)
{
    extern __shared__ float sm[];
    float (*Qs)[68] = (float(*)[68])(sm);
    float (*Ks)[68] = (float(*)[68])(sm + 128 * 68);
    float (*Vs)[68] = (float(*)[68])(sm + 192 * 68);
    float (*Ps)[68] = (float(*)[68])(sm + 256 * 68);

    int t  = threadIdx.x;
    int tx = t & 15, ty = t >> 4;
    int q0 = blockIdx.x << 7;
    int h  = blockIdx.y;
    int b  = blockIdx.z;

    const float* base = qkv + (long)b * L_ * D3 + h * HD_;

    for (int i = t; i < 128 * 16; i += 256) {
        int r = i >> 4, c4 = (i & 15) << 2;
        float4 v = *(const float4*)(base + (long)(q0 + r) * D3 + c4);
        v.x *= 0.125f; v.y *= 0.125f; v.z *= 0.125f; v.w *= 0.125f;
        *(float4*)&Qs[r][c4] = v;
    }

    float m[8], l[8], o[8][4];
    #pragma unroll
    for (int i = 0; i < 8; ++i) {
        m[i] = -1e30f; l[i] = 0.0f;
        o[i][0] = o[i][1] = o[i][2] = o[i][3] = 0.0f;
    }
    __syncthreads();

    for (int kt = 0; kt < 32; ++kt) {
        int k0 = kt << 6;
        for (int i = t; i < 64 * 16; i += 256) {
            int r = i >> 4, c4 = (i & 15) << 2;
            *(float4*)&Ks[r][c4] =
                *(const float4*)(base + D_     + (long)(k0 + r) * D3 + c4);
            *(float4*)&Vs[r][c4] =
                *(const float4*)(base + 2 * D_ + (long)(k0 + r) * D3 + c4);
        }
        __syncthreads();

        float s[8][4];
        #pragma unroll
        for (int i = 0; i < 8; ++i)
            s[i][0] = s[i][1] = s[i][2] = s[i][3] = 0.0f;

        #pragma unroll 4
        for (int d4 = 0; d4 < 64; d4 += 4) {
            float4 k0f = *(const float4*)&Ks[tx     ][d4];
            float4 k1f = *(const float4*)&Ks[tx + 16][d4];
            float4 k2f = *(const float4*)&Ks[tx + 32][d4];
            float4 k3f = *(const float4*)&Ks[tx + 48][d4];
            #pragma unroll
            for (int i = 0; i < 8; ++i) {
                float4 qf = *(const float4*)&Qs[ty * 8 + i][d4];
                s[i][0] += qf.x * k0f.x + qf.y * k0f.y + qf.z * k0f.z + qf.w * k0f.w;
                s[i][1] += qf.x * k1f.x + qf.y * k1f.y + qf.z * k1f.z + qf.w * k1f.w;
                s[i][2] += qf.x * k2f.x + qf.y * k2f.y + qf.z * k2f.z + qf.w * k2f.w;
                s[i][3] += qf.x * k3f.x + qf.y * k3f.y + qf.z * k3f.z + qf.w * k3f.w;
            }
        }

        #pragma unroll
        for (int i = 0; i < 8; ++i) {
            float mx = fmaxf(fmaxf(s[i][0], s[i][1]), fmaxf(s[i][2], s[i][3]));
            #pragma unroll
            for (int off = 8; off > 0; off >>= 1)
                mx = fmaxf(mx, __shfl_xor_sync(0xffffffffu, mx, off));
            float mn    = fmaxf(m[i], mx);
            float alpha = __expf(m[i] - mn);
            m[i] = mn;
            float p0 = __expf(s[i][0] - mn), p1 = __expf(s[i][1] - mn);
            float p2 = __expf(s[i][2] - mn), p3 = __expf(s[i][3] - mn);
            float sum = p0 + p1 + p2 + p3;
            #pragma unroll
            for (int off = 8; off > 0; off >>= 1)
                sum += __shfl_xor_sync(0xffffffffu, sum, off);
            l[i] = l[i] * alpha + sum;
            o[i][0] *= alpha; o[i][1] *= alpha; o[i][2] *= alpha; o[i][3] *= alpha;
            int r = ty * 8 + i;
            Ps[r][tx] = p0; Ps[r][tx + 16] = p1; Ps[r][tx + 32] = p2; Ps[r][tx + 48] = p3;
        }
        __syncthreads();

        #pragma unroll 8
        for (int k = 0; k < 64; ++k) {
            float4 vv = *(const float4*)&Vs[k][tx << 2];
            #pragma unroll
            for (int i = 0; i < 8; ++i) {
                float p = Ps[ty * 8 + i][k];
                o[i][0] += p * vv.x; o[i][1] += p * vv.y;
                o[i][2] += p * vv.z; o[i][3] += p * vv.w;
            }
        }
        __syncthreads();
    }

    #pragma unroll
    for (int i = 0; i < 8; ++i) {
        float inv = 1.0f / l[i];
        float4 v;
        v.x = o[i][0] * inv; v.y = o[i][1] * inv;
        v.z = o[i][2] * inv; v.w = o[i][3] * inv;
        long row  = (long)b * L_ + q0 + ty * 8 + i;
        long eoff = row * D_ + h * HD_ + (tx << 2);
        uint2 hv, lv;
        split4(v, hv, lv);
        *(uint2*)(out_hi + eoff) = hv;
        *(uint2*)(out_lo + eoff) = lv;
    }
}

// ---------------------------------------------------------------------------
// kernel_launch
// ---------------------------------------------------------------------------
extern "C" void kernel_launch(void* const* d_in, const int* in_sizes, int n_in,
                              void* d_out, int out_size)
{
    const float* zH     = (const float*)d_in[0];
    const float* zL     = (const float*)d_in[1];
    const float* w_qkv  = (const float*)d_in[2];
    const float* w_out  = (const float*)d_in[3];
    const float* w_ffn1 = (const float*)d_in[4];
    const float* w_ffn2 = (const float*)d_in[5];
    const float* g1     = (const float*)d_in[6];
    const float* g2     = (const float*)d_in[7];
    float* out = (float*)d_out;

    float *px, *pqkv;
    u16 *phh, *phl, *paoh, *paol, *pmh, *pml;
    u16 *pw1h, *pw1l, *pw2h, *pw2l, *pw3h, *pw3l, *pw4h, *pw4l;
    cudaGetSymbolAddress((void**)&px,   g_x);
    cudaGetSymbolAddress((void**)&pqkv, g_qkv);
    cudaGetSymbolAddress((void**)&phh,  g_h_hi);
    cudaGetSymbolAddress((void**)&phl,  g_h_lo);
    cudaGetSymbolAddress((void**)&paoh, g_ao_hi);
    cudaGetSymbolAddress((void**)&paol, g_ao_lo);
    cudaGetSymbolAddress((void**)&pmh,  g_mid_hi);
    cudaGetSymbolAddress((void**)&pml,  g_mid_lo);
    cudaGetSymbolAddress((void**)&pw1h, g_w1_hi);
    cudaGetSymbolAddress((void**)&pw1l, g_w1_lo);
    cudaGetSymbolAddress((void**)&pw2h, g_w2_hi);
    cudaGetSymbolAddress((void**)&pw2l, g_w2_lo);
    cudaGetSymbolAddress((void**)&pw3h, g_w3_hi);
    cudaGetSymbolAddress((void**)&pw3l, g_w3_lo);
    cudaGetSymbolAddress((void**)&pw4h, g_w4_hi);
    cudaGetSymbolAddress((void**)&pw4l, g_w4_lo);

    cudaFuncSetAttribute(flash_kernel,
                         cudaFuncAttributeMaxDynamicSharedMemorySize, FLASH_SMEM);
    cudaFuncSetAttribute(gemm_bf3<EPI_NONE>,
                         cudaFuncAttributeMaxDynamicSharedMemorySize, GEMM_SMEM);
    cudaFuncSetAttribute(gemm_bf3<EPI_SILU>,
                         cudaFuncAttributeMaxDynamicSharedMemorySize, GEMM_SMEM);
    cudaFuncSetAttribute(gemm_bf3<EPI_RES>,
                         cudaFuncAttributeMaxDynamicSharedMemorySize, GEMM_SMEM);

    // 0. weight split (bf16 hi/lo), once per launch
    splitw_kernel<<<(D3 * D_) / 1024, 256>>>(w_qkv,  pw1h, pw1l);
    splitw_kernel<<<(D_ * D_) / 1024, 256>>>(w_out,  pw2h, pw2l);
    splitw_kernel<<<(D4 * D_) / 1024, 256>>>(w_ffn1, pw3h, pw3l);
    splitw_kernel<<<(D_ * D4) / 1024, 256>>>(w_ffn2, pw4h, pw4l);

    // 1. x = zH + zL ; h = rmsnorm(x) * g1  (bf16 split)
    rmsnorm_kernel<true><<<ROWS, 256>>>(zH, zL, g1, px, phh, phl);

    // 2. qkv = h @ w_qkv^T                [4096, 3072] fp32
    gemm_bf3<EPI_NONE><<<dim3(D3 / 128, ROWS / 128), 256, GEMM_SMEM>>>(
        phh, phl, pw1h, pw1l, nullptr, pqkv, nullptr, nullptr, ROWS, D3, D_);

    // 3. RoPE on q, k (in place)
    rope_kernel<<<(B_ * L_ * 2 * H_ * 32) / 256, 256>>>(pqkv);

    // 4. attention -> ao (bf16 split)
    flash_kernel<<<dim3(L_ / 128, H_, B_), 256, FLASH_SMEM>>>(pqkv, paoh, paol);

    // 5. x2 = x + ao @ w_out^T            (in place into g_x)
    gemm_bf3<EPI_RES><<<dim3(D_ / 128, ROWS / 128), 256, GEMM_SMEM>>>(
        paoh, paol, pw2h, pw2l, px, px, nullptr, nullptr, ROWS, D_, D_);

    // 6. h2 = rmsnorm(x2) * g2 (bf16 split)
    rmsnorm_kernel<false><<<ROWS, 256>>>(px, nullptr, g2, nullptr, phh, phl);

    // 7. mid = silu(h2 @ w_ffn1^T)        [4096, 4096] bf16 split
    gemm_bf3<EPI_SILU><<<dim3(D4 / 128, ROWS / 128), 256, GEMM_SMEM>>>(
        phh, phl, pw3h, pw3l, nullptr, nullptr, pmh, pml, ROWS, D4, D_);

    // 8. out = x2 + mid @ w_ffn2^T        [4096, 1024] fp32, K = 4096
    gemm_bf3<EPI_RES><<<dim3(D_ / 128, ROWS / 128), 256, GEMM_SMEM>>>(
        pmh, pml, pw4h, pw4l, px, out, nullptr, nullptr, ROWS, D_, D4);
}

// round 13
// speedup vs baseline: 1.9002x; 1.0007x over previous
#include <cuda_runtime.h>
#include <cuda_bf16.h>
#include <math.h>
#include <cstdint>

// Problem constants
#define B_   2
#define L_   2048
#define D_   1024
#define H_   16
#define HD_  64
#define ROWS (B_ * L_)          // 4096
#define D3   (3 * D_)           // 3072
#define D4   (4 * D_)           // 4096

typedef unsigned short u16;

// ---------------------------------------------------------------------------
// Scratch (static __device__ arrays — no allocation allowed)
// ---------------------------------------------------------------------------
__device__ float g_x  [ROWS * D_];   // residual stream (fp32)
__device__ float g_qkv[ROWS * D3];   // qkv (fp32, consumed by rope/flash)

__device__ u16 g_h_hi [ROWS * D_],  g_h_lo [ROWS * D_];   // rmsnorm out (bf16 split)
__device__ u16 g_ao_hi[ROWS * D_],  g_ao_lo[ROWS * D_];   // attention out
__device__ u16 g_mid_hi[ROWS * D4], g_mid_lo[ROWS * D4];  // ffn intermediate

__device__ u16 g_w1_hi[D3 * D_], g_w1_lo[D3 * D_];        // w_qkv
__device__ u16 g_w2_hi[D_ * D_], g_w2_lo[D_ * D_];        // w_out
__device__ u16 g_w3_hi[D4 * D_], g_w3_lo[D4 * D_];        // w_ffn1
__device__ u16 g_w4_hi[D_ * D4], g_w4_lo[D_ * D4];        // w_ffn2

// ---------------------------------------------------------------------------
// PTX helpers (baseline ISA only — target is compute_103, no tcgen05)
// ---------------------------------------------------------------------------
__device__ __forceinline__ uint32_t smem_u32(const void* p) {
    uint32_t a;
    asm("{ .reg .u64 t; cvta.to.shared.u64 t, %1; cvt.u32.u64 %0, t; }"
        : "=r"(a) : "l"(p));
    return a;
}

#define LDSM_X4(R0, R1, R2, R3, ADDR)                                         \
    asm volatile("ldmatrix.sync.aligned.m8n8.x4.shared.b16 {%0,%1,%2,%3}, [%4];" \
                 : "=r"(R0), "=r"(R1), "=r"(R2), "=r"(R3) : "r"(ADDR))

#define MMA_BF16(c, a, b)                                                     \
    asm volatile("mma.sync.aligned.m16n8k16.row.col.f32.bf16.bf16.f32 "       \
                 "{%0,%1,%2,%3}, {%4,%5,%6,%7}, {%8,%9}, {%0,%1,%2,%3};"      \
                 : "+f"((c)[0]), "+f"((c)[1]), "+f"((c)[2]), "+f"((c)[3])     \
                 : "r"((a)[0]), "r"((a)[1]), "r"((a)[2]), "r"((a)[3]),        \
                   "r"((b)[0]), "r"((b)[1]))

#define CP16(s, g)  asm volatile("cp.async.cg.shared.global [%0], [%1], 16;" \
                                 :: "r"(s), "l"(g))
#define CP_COMMIT() asm volatile("cp.async.commit_group;")
#define CP_WAIT1()  asm volatile("cp.async.wait_group 1;")
#define CP_WAIT0()  asm volatile("cp.async.wait_group 0;")

// ---------------------------------------------------------------------------
// bf16 hi/lo split helpers
// ---------------------------------------------------------------------------
__device__ __forceinline__ uint32_t pack_bf2(__nv_bfloat16 a, __nv_bfloat16 b) {
    return (uint32_t)__bfloat16_as_ushort(a) |
           ((uint32_t)__bfloat16_as_ushort(b) << 16);
}

__device__ __forceinline__ void split4(float4 v, uint2& hv, uint2& lv) {
    __nv_bfloat16 h0 = __float2bfloat16(v.x), h1 = __float2bfloat16(v.y);
    __nv_bfloat16 h2 = __float2bfloat16(v.z), h3 = __float2bfloat16(v.w);
    hv.x = pack_bf2(h0, h1);
    hv.y = pack_bf2(h2, h3);
    __nv_bfloat16 l0 = __float2bfloat16(v.x - __bfloat162float(h0));
    __nv_bfloat16 l1 = __float2bfloat16(v.y - __bfloat162float(h1));
    __nv_bfloat16 l2 = __float2bfloat16(v.z - __bfloat162float(h2));
    __nv_bfloat16 l3 = __float2bfloat16(v.w - __bfloat162float(h3));
    lv.x = pack_bf2(l0, l1);
    lv.y = pack_bf2(l2, l3);
}

// weight split: fp32 -> bf16 hi/lo (4 elements per thread)
__global__ void splitw_kernel(const float* __restrict__ w,
                              u16* __restrict__ hi, u16* __restrict__ lo)
{
    long i = (long)blockIdx.x * blockDim.x + threadIdx.x;
    float4 v = ((const float4*)w)[i];
    uint2 hv, lv;
    split4(v, hv, lv);
    ((uint2*)hi)[i] = hv;
    ((uint2*)lo)[i] = lv;
}

// ---------------------------------------------------------------------------
// Fused (optional add) + RMSNorm -> bf16 split output.
// ---------------------------------------------------------------------------
template <bool ADD>
__global__ void rmsnorm_kernel(const float* __restrict__ A,
                               const float* __restrict__ Bp,
                               const float* __restrict__ g,
                               float* __restrict__ x_out,
                               u16* __restrict__ h_hi,
                               u16* __restrict__ h_lo)
{
    int row = blockIdx.x;
    int t   = threadIdx.x;
    long base = (long)row * D_;

    float4 x = ((const float4*)(A + base))[t];
    if (ADD) {
        float4 b = ((const float4*)(Bp + base))[t];
        x.x += b.x; x.y += b.y; x.z += b.z; x.w += b.w;
    }
    float ss = x.x * x.x + x.y * x.y + x.z * x.z + x.w * x.w;
    #pragma unroll
    for (int off = 16; off > 0; off >>= 1)
        ss += __shfl_xor_sync(0xffffffffu, ss, off);

    __shared__ float sw[8];
    if ((t & 31) == 0) sw[t >> 5] = ss;
    __syncthreads();
    float tot = sw[0] + sw[1] + sw[2] + sw[3] + sw[4] + sw[5] + sw[6] + sw[7];
    float r = rsqrtf(tot * (1.0f / (float)D_) + 1e-6f);

    float4 gg = ((const float4*)g)[t];
    float4 h;
    h.x = x.x * r * gg.x;  h.y = x.y * r * gg.y;
    h.z = x.z * r * gg.z;  h.w = x.w * r * gg.w;

    if (ADD) ((float4*)(x_out + base))[t] = x;
    uint2 hv, lv;
    split4(h, hv, lv);
    ((uint2*)h_hi)[row * 256 + t] = hv;
    ((uint2*)h_lo)[row * 256 + t] = lv;
}

// ---------------------------------------------------------------------------
// bf16-split tensor-core GEMM v2:  C = epi( A[M,K] * B[N,K]^T )
// Operands pre-split in gmem (bf16 hi/lo).  3 terms: AhBh + AlBh + AhBl.
// CTA 128x128, K-chunk 32, 8 warps (2M x 4N), warp tile 64x32.
// cp.async 3-stage pipeline; smem rows 64B; swizzle u ^= (row>>1)&3
// (conflict-free for ldmatrix m8n8 and cp.async stores).
// ---------------------------------------------------------------------------
#define EPI_NONE 0
#define EPI_SILU 1
#define EPI_RES  2

#define GEMM_STG   32768           // bytes per stage (4 tiles x 8KB)
#define GEMM_SMEM  (3 * GEMM_STG)  // 96KB

__device__ __forceinline__ uint32_t swz(int row, int u) {
    return (uint32_t)(row * 64 + ((u ^ ((row >> 1) & 3)) << 4));
}

template <int EPI>
__global__ void __launch_bounds__(256) gemm_bf3(
    const u16* __restrict__ Ah, const u16* __restrict__ Al,
    const u16* __restrict__ Bh, const u16* __restrict__ Bl,
    const float* __restrict__ R, float* __restrict__ C,
    u16* __restrict__ Chi, u16* __restrict__ Clo,
    int M, int N, int K)
{
    extern __shared__ char smx[];
    uint32_t sb = smem_u32(smx);

    int t   = threadIdx.x;
    int ln  = t & 31;
    int wid = t >> 5;
    int wm  = wid >> 2;
    int wn  = wid & 3;
    int bm  = blockIdx.y << 7;
    int bn  = blockIdx.x << 7;

    // loader: row = t>>1, units u = (t&1)*2 + {0,1}
    int lrow = t >> 1;
    int lu0  = (t & 1) << 1;
    const u16* gAh = Ah + (long)(bm + lrow) * K;
    const u16* gAl = Al + (long)(bm + lrow) * K;
    const u16* gBh = Bh + (long)(bn + lrow) * K;
    const u16* gBl = Bl + (long)(bn + lrow) * K;
    uint32_t so0 = swz(lrow, lu0);
    uint32_t so1 = swz(lrow, lu0 + 1);
    int go0 = lu0 * 8, go1 = lu0 * 8 + 8;

    float acc[4][4][4];
    #pragma unroll
    for (int i = 0; i < 4; ++i)
        #pragma unroll
        for (int j = 0; j < 4; ++j)
            acc[i][j][0] = acc[i][j][1] = acc[i][j][2] = acc[i][j][3] = 0.0f;

    int nc = K >> 5;

    // prologue: stages 0,1
    {
        uint32_t b0 = sb;
        CP16(b0 + so0,         gAh + go0);  CP16(b0 + so1,         gAh + go1);
        CP16(b0 + 8192 + so0,  gAl + go0);  CP16(b0 + 8192 + so1,  gAl + go1);
        CP16(b0 + 16384 + so0, gBh + go0);  CP16(b0 + 16384 + so1, gBh + go1);
        CP16(b0 + 24576 + so0, gBl + go0);  CP16(b0 + 24576 + so1, gBl + go1);
        CP_COMMIT();
        if (nc > 1) {
            uint32_t b1 = sb + GEMM_STG;
            CP16(b1 + so0,         gAh + 32 + go0);  CP16(b1 + so1,         gAh + 32 + go1);
            CP16(b1 + 8192 + so0,  gAl + 32 + go0);  CP16(b1 + 8192 + so1,  gAl + 32 + go1);
            CP16(b1 + 16384 + so0, gBh + 32 + go0);  CP16(b1 + 16384 + so1, gBh + 32 + go1);
            CP16(b1 + 24576 + so0, gBl + 32 + go0);  CP16(b1 + 24576 + so1, gBl + 32 + go1);
            CP_COMMIT();
        }
    }

    // ldmatrix lane geometry
    int a_row = ln & 15;
    int a_k8  = ln >> 4;
    int gq    = ln >> 3;
    int b_row = ((gq >> 1) << 3) + (ln & 7);
    int b_k8  = gq & 1;

    int stage = 0;
    for (int c = 0; c < nc; ++c) {
        if (c + 1 < nc) { CP_WAIT1(); } else { CP_WAIT0(); }
        __syncthreads();

        if (c + 2 < nc) {
            int ns = stage + 2; if (ns >= 3) ns -= 3;
            uint32_t nb = sb + ns * GEMM_STG;
            long ko = (long)(c + 2) * 32;
            CP16(nb + so0,         gAh + ko + go0);  CP16(nb + so1,         gAh + ko + go1);
            CP16(nb + 8192 + so0,  gAl + ko + go0);  CP16(nb + 8192 + so1,  gAl + ko + go1);
            CP16(nb + 16384 + so0, gBh + ko + go0);  CP16(nb + 16384 + so1, gBh + ko + go1);
            CP16(nb + 24576 + so0, gBl + ko + go0);  CP16(nb + 24576 + so1, gBl + ko + go1);
            CP_COMMIT();
        }

        uint32_t uAh = sb + stage * GEMM_STG;
        uint32_t uAl = uAh + 8192;
        uint32_t uBh = uAh + 16384;
        uint32_t uBl = uAh + 24576;

        #pragma unroll
        for (int kh = 0; kh < 2; ++kh) {
            uint32_t ah[4][4], al[4][4], bh[4][2], bl[4][2];

            #pragma unroll
            for (int mt = 0; mt < 4; ++mt) {
                int row = wm * 64 + mt * 16 + a_row;
                uint32_t off = swz(row, kh * 2 + a_k8);
                LDSM_X4(ah[mt][0], ah[mt][1], ah[mt][2], ah[mt][3], uAh + off);
                LDSM_X4(al[mt][0], al[mt][1], al[mt][2], al[mt][3], uAl + off);
            }
            #pragma unroll
            for (int np = 0; np < 2; ++np) {
                int row = wn * 32 + np * 16 + b_row;
                uint32_t off = swz(row, kh * 2 + b_k8);
                uint32_t r0, r1, r2, r3;
                LDSM_X4(r0, r1, r2, r3, uBh + off);
                bh[np * 2][0] = r0; bh[np * 2][1] = r1;
                bh[np * 2 + 1][0] = r2; bh[np * 2 + 1][1] = r3;
                LDSM_X4(r0, r1, r2, r3, uBl + off);
                bl[np * 2][0] = r0; bl[np * 2][1] = r1;
                bl[np * 2 + 1][0] = r2; bl[np * 2 + 1][1] = r3;
            }

            #pragma unroll
            for (int mt = 0; mt < 4; ++mt)
                #pragma unroll
                for (int nt = 0; nt < 4; ++nt)
                    MMA_BF16(acc[mt][nt], ah[mt], bh[nt]);
            #pragma unroll
            for (int mt = 0; mt < 4; ++mt)
                #pragma unroll
                for (int nt = 0; nt < 4; ++nt)
                    MMA_BF16(acc[mt][nt], al[mt], bh[nt]);
            #pragma unroll
            for (int mt = 0; mt < 4; ++mt)
                #pragma unroll
                for (int nt = 0; nt < 4; ++nt)
                    MMA_BF16(acc[mt][nt], ah[mt], bl[nt]);
        }

        ++stage; if (stage == 3) stage = 0;
    }

    // epilogue
    int er = ln >> 2;
    int ec = (ln & 3) << 1;
    #pragma unroll
    for (int mt = 0; mt < 4; ++mt) {
        #pragma unroll
        for (int nt = 0; nt < 4; ++nt) {
            long row0 = bm + wm * 64 + mt * 16 + er;
            long col  = bn + wn * 32 + nt * 8 + ec;
            #pragma unroll
            for (int hrow = 0; hrow < 2; ++hrow) {
                long off = (row0 + hrow * 8) * (long)N + col;
                float vx = acc[mt][nt][hrow * 2 + 0];
                float vy = acc[mt][nt][hrow * 2 + 1];
                if (EPI == EPI_SILU) {
                    vx = vx / (1.0f + __expf(-vx));
                    vy = vy / (1.0f + __expf(-vy));
                    __nv_bfloat16 hx = __float2bfloat16(vx);
                    __nv_bfloat16 hy = __float2bfloat16(vy);
                    *(uint32_t*)(Chi + off) = pack_bf2(hx, hy);
                    *(uint32_t*)(Clo + off) = pack_bf2(
                        __float2bfloat16(vx - __bfloat162float(hx)),
                        __float2bfloat16(vy - __bfloat162float(hy)));
                } else {
                    if (EPI == EPI_RES) {
                        float2 rr = *(const float2*)(R + off);
                        vx += rr.x; vy += rr.y;
                    }
                    float2 v; v.x = vx; v.y = vy;
                    *(float2*)(C + off) = v;
                }
            }
        }
    }
}

// ---------------------------------------------------------------------------
// RoPE applied in place to q and k segments of g_qkv.
// ---------------------------------------------------------------------------
__global__ void rope_kernel(float* __restrict__ qkv)
{
    int idx = blockIdx.x * blockDim.x + threadIdx.x;
    int j  = idx & 31;
    int hh = (idx >> 5) & 15;
    int s  = (idx >> 9) & 1;
    int l  = (idx >> 10) & 2047;
    int b  = idx >> 21;

    double dinv = exp(-(double)j * (9.210340371976184 / 32.0));
    float  invf = (float)dinv;
    float  fr   = (float)l * invf;
    float sn, cs;
    sincosf(fr, &sn, &cs);

    long base = (long)(b * L_ + l) * D3 + s * D_ + hh * HD_ + j;
    float x1 = qkv[base];
    float x2 = qkv[base + 32];
    qkv[base]      = x1 * cs - x2 * sn;
    qkv[base + 32] = x2 * cs + x1 * sn;
}

// ---------------------------------------------------------------------------
// Flash attention, fp32 (epilogue now writes bf16 hi/lo for the out-proj GEMM)
// ---------------------------------------------------------------------------
#define FLASH_SMEM (384 * 68 * 4)

__global__ void __launch_bounds__(256) flash_kernel(
    const float* __restrict__ qkv,
    u16* __restrict__ out_hi, u16* __restrict__ out_lo)
{
    extern __shared__ float sm[];
    float (*Qs)[68] = (float(*)[68])(sm);
    float (*Ks)[68] = (float(*)[68])(sm + 128 * 68);
    float (*Vs)[68] = (float(*)[68])(sm + 192 * 68);
    float (*Ps)[68] = (float(*)[68])(sm + 256 * 68);

    int t  = threadIdx.x;
    int tx = t & 15, ty = t >> 4;
    int q0 = blockIdx.x << 7;
    int h  = blockIdx.y;
    int b  = blockIdx.z;

    const float* base = qkv + (long)b * L_ * D3 + h * HD_;

    for (int i = t; i < 128 * 16; i += 256) {
        int r = i >> 4, c4 = (i & 15) << 2;
        float4 v = *(const float4*)(base + (long)(q0 + r) * D3 + c4);
        v.x *= 0.125f; v.y *= 0.125f; v.z *= 0.125f; v.w *= 0.125f;
        *(float4*)&Qs[r][c4] = v;
    }

    float m[8], l[8], o[8][4];
    #pragma unroll
    for (int i = 0; i < 8; ++i) {
        m[i] = -1e30f; l[i] = 0.0f;
        o[i][0] = o[i][1] = o[i][2] = o[i][3] = 0.0f;
    }
    __syncthreads();

    for (int kt = 0; kt < 32; ++kt) {
        int k0 = kt << 6;
        for (int i = t; i < 64 * 16; i += 256) {
            int r = i >> 4, c4 = (i & 15) << 2;
            *(float4*)&Ks[r][c4] =
                *(const float4*)(base + D_     + (long)(k0 + r) * D3 + c4);
            *(float4*)&Vs[r][c4] =
                *(const float4*)(base + 2 * D_ + (long)(k0 + r) * D3 + c4);
        }
        __syncthreads();

        float s[8][4];
        #pragma unroll
        for (int i = 0; i < 8; ++i)
            s[i][0] = s[i][1] = s[i][2] = s[i][3] = 0.0f;

        #pragma unroll 4
        for (int d4 = 0; d4 < 64; d4 += 4) {
            float4 k0f = *(const float4*)&Ks[tx     ][d4];
            float4 k1f = *(const float4*)&Ks[tx + 16][d4];
            float4 k2f = *(const float4*)&Ks[tx + 32][d4];
            float4 k3f = *(const float4*)&Ks[tx + 48][d4];
            #pragma unroll
            for (int i = 0; i < 8; ++i) {
                float4 qf = *(const float4*)&Qs[ty * 8 + i][d4];
                s[i][0] += qf.x * k0f.x + qf.y * k0f.y + qf.z * k0f.z + qf.w * k0f.w;
                s[i][1] += qf.x * k1f.x + qf.y * k1f.y + qf.z * k1f.z + qf.w * k1f.w;
                s[i][2] += qf.x * k2f.x + qf.y * k2f.y + qf.z * k2f.z + qf.w * k2f.w;
                s[i][3] += qf.x * k3f.x + qf.y * k3f.y + qf.z * k3f.z + qf.w * k3f.w;
            }
        }

        #pragma unroll
        for (int i = 0; i < 8; ++i) {
            float mx = fmaxf(fmaxf(s[i][0], s[i][1]), fmaxf(s[i][2], s[i][3]));
            #pragma unroll
            for (int off = 8; off > 0; off >>= 1)
                mx = fmaxf(mx, __shfl_xor_sync(0xffffffffu, mx, off));
            float mn    = fmaxf(m[i], mx);
            float alpha = __expf(m[i] - mn);
            m[i] = mn;
            float p0 = __expf(s[i][0] - mn), p1 = __expf(s[i][1] - mn);
            float p2 = __expf(s[i][2] - mn), p3 = __expf(s[i][3] - mn);
            float sum = p0 + p1 + p2 + p3;
            #pragma unroll
            for (int off = 8; off > 0; off >>= 1)
                sum += __shfl_xor_sync(0xffffffffu, sum, off);
            l[i] = l[i] * alpha + sum;
            o[i][0] *= alpha; o[i][1] *= alpha; o[i][2] *= alpha; o[i][3] *= alpha;
            int r = ty * 8 + i;
            Ps[r][tx] = p0; Ps[r][tx + 16] = p1; Ps[r][tx + 32] = p2; Ps[r][tx + 48] = p3;
        }
        __syncthreads();

        #pragma unroll 8
        for (int k = 0; k < 64; ++k) {
            float4 vv = *(const float4*)&Vs[k][tx << 2];
            #pragma unroll
            for (int i = 0; i < 8; ++i) {
                float p = Ps[ty * 8 + i][k];
                o[i][0] += p * vv.x; o[i][1] += p * vv.y;
                o[i][2] += p * vv.z; o[i][3] += p * vv.w;
            }
        }
        __syncthreads();
    }

    #pragma unroll
    for (int i = 0; i < 8; ++i) {
        float inv = 1.0f / l[i];
        float4 v;
        v.x = o[i][0] * inv; v.y = o[i][1] * inv;
        v.z = o[i][2] * inv; v.w = o[i][3] * inv;
        long row  = (long)b * L_ + q0 + ty * 8 + i;
        long eoff = row * D_ + h * HD_ + (tx << 2);
        uint2 hv, lv;
        split4(v, hv, lv);
        *(uint2*)(out_hi + eoff) = hv;
        *(uint2*)(out_lo + eoff) = lv;
    }
}

// ---------------------------------------------------------------------------
// kernel_launch
// ---------------------------------------------------------------------------
extern "C" void kernel_launch(void* const* d_in, const int* in_sizes, int n_in,
                              void* d_out, int out_size)
{
    const float* zH     = (const float*)d_in[0];
    const float* zL     = (const float*)d_in[1];
    const float* w_qkv  = (const float*)d_in[2];
    const float* w_out  = (const float*)d_in[3];
    const float* w_ffn1 = (const float*)d_in[4];
    const float* w_ffn2 = (const float*)d_in[5];
    const float* g1     = (const float*)d_in[6];
    const float* g2     = (const float*)d_in[7];
    float* out = (float*)d_out;

    float *px, *pqkv;
    u16 *phh, *phl, *paoh, *paol, *pmh, *pml;
    u16 *pw1h, *pw1l, *pw2h, *pw2l, *pw3h, *pw3l, *pw4h, *pw4l;
    cudaGetSymbolAddress((void**)&px,   g_x);
    cudaGetSymbolAddress((void**)&pqkv, g_qkv);
    cudaGetSymbolAddress((void**)&phh,  g_h_hi);
    cudaGetSymbolAddress((void**)&phl,  g_h_lo);
    cudaGetSymbolAddress((void**)&paoh, g_ao_hi);
    cudaGetSymbolAddress((void**)&paol, g_ao_lo);
    cudaGetSymbolAddress((void**)&pmh,  g_mid_hi);
    cudaGetSymbolAddress((void**)&pml,  g_mid_lo);
    cudaGetSymbolAddress((void**)&pw1h, g_w1_hi);
    cudaGetSymbolAddress((void**)&pw1l, g_w1_lo);
    cudaGetSymbolAddress((void**)&pw2h, g_w2_hi);
    cudaGetSymbolAddress((void**)&pw2l, g_w2_lo);
    cudaGetSymbolAddress((void**)&pw3h, g_w3_hi);
    cudaGetSymbolAddress((void**)&pw3l, g_w3_lo);
    cudaGetSymbolAddress((void**)&pw4h, g_w4_hi);
    cudaGetSymbolAddress((void**)&pw4l, g_w4_lo);

    cudaFuncSetAttribute(flash_kernel,
                         cudaFuncAttributeMaxDynamicSharedMemorySize, FLASH_SMEM);
    cudaFuncSetAttribute(gemm_bf3<EPI_NONE>,
                         cudaFuncAttributeMaxDynamicSharedMemorySize, GEMM_SMEM);
    cudaFuncSetAttribute(gemm_bf3<EPI_SILU>,
                         cudaFuncAttributeMaxDynamicSharedMemorySize, GEMM_SMEM);
    cudaFuncSetAttribute(gemm_bf3<EPI_RES>,
                         cudaFuncAttributeMaxDynamicSharedMemorySize, GEMM_SMEM);

    // 0. weight split (bf16 hi/lo), once per launch
    splitw_kernel<<<(D3 * D_) / 1024, 256>>>(w_qkv,  pw1h, pw1l);
    splitw_kernel<<<(D_ * D_) / 1024, 256>>>(w_out,  pw2h, pw2l);
    splitw_kernel<<<(D4 * D_) / 1024, 256>>>(w_ffn1, pw3h, pw3l);
    splitw_kernel<<<(D_ * D4) / 1024, 256>>>(w_ffn2, pw4h, pw4l);

    // 1. x = zH + zL ; h = rmsnorm(x) * g1  (bf16 split)
    rmsnorm_kernel<true><<<ROWS, 256>>>(zH, zL, g1, px, phh, phl);

    // 2. qkv = h @ w_qkv^T                [4096, 3072] fp32
    gemm_bf3<EPI_NONE><<<dim3(D3 / 128, ROWS / 128), 256, GEMM_SMEM>>>(
        phh, phl, pw1h, pw1l, nullptr, pqkv, nullptr, nullptr, ROWS, D3, D_);

    // 3. RoPE on q, k (in place)
    rope_kernel<<<(B_ * L_ * 2 * H_ * 32) / 256, 256>>>(pqkv);

    // 4. attention -> ao (bf16 split)
    flash_kernel<<<dim3(L_ / 128, H_, B_), 256, FLASH_SMEM>>>(pqkv, paoh, paol);

    // 5. x2 = x + ao @ w_out^T            (in place into g_x)
    gemm_bf3<EPI_RES><<<dim3(D_ / 128, ROWS / 128), 256, GEMM_SMEM>>>(
        paoh, paol, pw2h, pw2l, px, px, nullptr, nullptr, ROWS, D_, D_);

    // 6. h2 = rmsnorm(x2) * g2 (bf16 split)
    rmsnorm_kernel<false><<<ROWS, 256>>>(px, nullptr, g2, nullptr, phh, phl);

    // 7. mid = silu(h2 @ w_ffn1^T)        [4096, 4096] bf16 split
    gemm_bf3<EPI_SILU><<<dim3(D4 / 128, ROWS / 128), 256, GEMM_SMEM>>>(
        phh, phl, pw3h, pw3l, nullptr, nullptr, pmh, pml, ROWS, D4, D_);

    // 8. out = x2 + mid @ w_ffn2^T        [4096, 1024] fp32, K = 4096
    gemm_bf3<EPI_RES><<<dim3(D_ / 128, ROWS / 128), 256, GEMM_SMEM>>>(
        pmh, pml, pw4h, pw4l, px, out, nullptr, nullptr, ROWS, D_, D4);
}

// round 14
// speedup vs baseline: 1.9008x; 1.0003x over previous
#include <cuda_runtime.h>
#include <cuda_bf16.h>
#include <math.h>
#include <cstdint>

// Problem constants
#define B_   2
#define L_   2048
#define D_   1024
#define H_   16
#define HD_  64
#define ROWS (B_ * L_)          // 4096
#define D3   (3 * D_)           // 3072
#define D4   (4 * D_)           // 4096

typedef unsigned short u16;

// ---------------------------------------------------------------------------
// Scratch (static __device__ arrays — no allocation allowed)
// ---------------------------------------------------------------------------
__device__ float g_x  [ROWS * D_];   // residual stream (fp32)
__device__ float g_qkv[ROWS * D3];   // qkv (fp32, consumed by rope/flash)

__device__ u16 g_h_hi [ROWS * D_],  g_h_lo [ROWS * D_];   // rmsnorm out (bf16 split)
__device__ u16 g_ao_hi[ROWS * D_],  g_ao_lo[ROWS * D_];   // attention out
__device__ u16 g_mid_hi[ROWS * D4], g_mid_lo[ROWS * D4];  // ffn intermediate

__device__ u16 g_w1_hi[D3 * D_], g_w1_lo[D3 * D_];        // w_qkv
__device__ u16 g_w2_hi[D_ * D_], g_w2_lo[D_ * D_];        // w_out
__device__ u16 g_w3_hi[D4 * D_], g_w3_lo[D4 * D_];        // w_ffn1
__device__ u16 g_w4_hi[D_ * D4], g_w4_lo[D_ * D4];        // w_ffn2

// ---------------------------------------------------------------------------
// PTX helpers (baseline ISA only — target is compute_103, no tcgen05)
// ---------------------------------------------------------------------------
__device__ __forceinline__ uint32_t smem_u32(const void* p) {
    uint32_t a;
    asm("{ .reg .u64 t; cvta.to.shared.u64 t, %1; cvt.u32.u64 %0, t; }"
        : "=r"(a) : "l"(p));
    return a;
}

#define LDSM_X4(R0, R1, R2, R3, ADDR)                                         \
    asm volatile("ldmatrix.sync.aligned.m8n8.x4.shared.b16 {%0,%1,%2,%3}, [%4];" \
                 : "=r"(R0), "=r"(R1), "=r"(R2), "=r"(R3) : "r"(ADDR))

#define MMA_BF16(c, a, b)                                                     \
    asm volatile("mma.sync.aligned.m16n8k16.row.col.f32.bf16.bf16.f32 "       \
                 "{%0,%1,%2,%3}, {%4,%5,%6,%7}, {%8,%9}, {%0,%1,%2,%3};"      \
                 : "+f"((c)[0]), "+f"((c)[1]), "+f"((c)[2]), "+f"((c)[3])     \
                 : "r"((a)[0]), "r"((a)[1]), "r"((a)[2]), "r"((a)[3]),        \
                   "r"((b)[0]), "r"((b)[1]))

#define CP16(s, g)  asm volatile("cp.async.cg.shared.global [%0], [%1], 16;" \
                                 :: "r"(s), "l"(g))
#define CP_COMMIT() asm volatile("cp.async.commit_group;")
#define CP_WAIT1()  asm volatile("cp.async.wait_group 1;")
#define CP_WAIT0()  asm volatile("cp.async.wait_group 0;")

// ---------------------------------------------------------------------------
// bf16 hi/lo split helpers
// ---------------------------------------------------------------------------
__device__ __forceinline__ uint32_t pack_bf2(__nv_bfloat16 a, __nv_bfloat16 b) {
    return (uint32_t)__bfloat16_as_ushort(a) |
           ((uint32_t)__bfloat16_as_ushort(b) << 16);
}

__device__ __forceinline__ void split4(float4 v, uint2& hv, uint2& lv) {
    __nv_bfloat16 h0 = __float2bfloat16(v.x), h1 = __float2bfloat16(v.y);
    __nv_bfloat16 h2 = __float2bfloat16(v.z), h3 = __float2bfloat16(v.w);
    hv.x = pack_bf2(h0, h1);
    hv.y = pack_bf2(h2, h3);
    __nv_bfloat16 l0 = __float2bfloat16(v.x - __bfloat162float(h0));
    __nv_bfloat16 l1 = __float2bfloat16(v.y - __bfloat162float(h1));
    __nv_bfloat16 l2 = __float2bfloat16(v.z - __bfloat162float(h2));
    __nv_bfloat16 l3 = __float2bfloat16(v.w - __bfloat162float(h3));
    lv.x = pack_bf2(l0, l1);
    lv.y = pack_bf2(l2, l3);
}

// weight split: fp32 -> bf16 hi/lo (4 elements per thread)
__global__ void splitw_kernel(const float* __restrict__ w,
                              u16* __restrict__ hi, u16* __restrict__ lo)
{
    long i = (long)blockIdx.x * blockDim.x + threadIdx.x;
    float4 v = ((const float4*)w)[i];
    uint2 hv, lv;
    split4(v, hv, lv);
    ((uint2*)hi)[i] = hv;
    ((uint2*)lo)[i] = lv;
}

// ---------------------------------------------------------------------------
// Fused (optional add) + RMSNorm -> bf16 split output.
// ---------------------------------------------------------------------------
template <bool ADD>
__global__ void rmsnorm_kernel(const float* __restrict__ A,
                               const float* __restrict__ Bp,
                               const float* __restrict__ g,
                               float* __restrict__ x_out,
                               u16* __restrict__ h_hi,
                               u16* __restrict__ h_lo)
{
    int row = blockIdx.x;
    int t   = threadIdx.x;
    long base = (long)row * D_;

    float4 x = ((const float4*)(A + base))[t];
    if (ADD) {
        float4 b = ((const float4*)(Bp + base))[t];
        x.x += b.x; x.y += b.y; x.z += b.z; x.w += b.w;
    }
    float ss = x.x * x.x + x.y * x.y + x.z * x.z + x.w * x.w;
    #pragma unroll
    for (int off = 16; off > 0; off >>= 1)
        ss += __shfl_xor_sync(0xffffffffu, ss, off);

    __shared__ float sw[8];
    if ((t & 31) == 0) sw[t >> 5] = ss;
    __syncthreads();
    float tot = sw[0] + sw[1] + sw[2] + sw[3] + sw[4] + sw[5] + sw[6] + sw[7];
    float r = rsqrtf(tot * (1.0f / (float)D_) + 1e-6f);

    float4 gg = ((const float4*)g)[t];
    float4 h;
    h.x = x.x * r * gg.x;  h.y = x.y * r * gg.y;
    h.z = x.z * r * gg.z;  h.w = x.w * r * gg.w;

    if (ADD) ((float4*)(x_out + base))[t] = x;
    uint2 hv, lv;
    split4(h, hv, lv);
    ((uint2*)h_hi)[row * 256 + t] = hv;
    ((uint2*)h_lo)[row * 256 + t] = lv;
}

// ---------------------------------------------------------------------------
// bf16-split tensor-core GEMM v2:  C = epi( A[M,K] * B[N,K]^T )
// Operands pre-split in gmem (bf16 hi/lo).  3 terms: AhBh + AlBh + AhBl.
// CTA 128x128, K-chunk 32, 8 warps (2M x 4N), warp tile 64x32.
// cp.async 3-stage pipeline; smem rows 64B; swizzle u ^= (row>>1)&3
// (conflict-free for ldmatrix m8n8 and cp.async stores).
// ---------------------------------------------------------------------------
#define EPI_NONE 0
#define EPI_SILU 1
#define EPI_RES  2

#define GEMM_STG   32768           // bytes per stage (4 tiles x 8KB)
#define GEMM_SMEM  (3 * GEMM_STG)  // 96KB

__device__ __forceinline__ uint32_t swz(int row, int u) {
    return (uint32_t)(row * 64 + ((u ^ ((row >> 1) & 3)) << 4));
}

template <int EPI>
__global__ void __launch_bounds__(256) gemm_bf3(
    const u16* __restrict__ Ah, const u16* __restrict__ Al,
    const u16* __restrict__ Bh, const u16* __restrict__ Bl,
    const float* __restrict__ R, float* __restrict__ C,
    u16* __restrict__ Chi, u16* __restrict__ Clo,
    int M, int N, int K)
{
    extern __shared__ char smx[];
    uint32_t sb = smem_u32(smx);

    int t   = threadIdx.x;
    int ln  = t & 31;
    int wid = t >> 5;
    int wm  = wid >> 2;
    int wn  = wid & 3;
    int bm  = blockIdx.y << 7;
    int bn  = blockIdx.x << 7;

    // loader: row = t>>1, units u = (t&1)*2 + {0,1}
    int lrow = t >> 1;
    int lu0  = (t & 1) << 1;
    const u16* gAh = Ah + (long)(bm + lrow) * K;
    const u16* gAl = Al + (long)(bm + lrow) * K;
    const u16* gBh = Bh + (long)(bn + lrow) * K;
    const u16* gBl = Bl + (long)(bn + lrow) * K;
    uint32_t so0 = swz(lrow, lu0);
    uint32_t so1 = swz(lrow, lu0 + 1);
    int go0 = lu0 * 8, go1 = lu0 * 8 + 8;

    float acc[4][4][4];
    #pragma unroll
    for (int i = 0; i < 4; ++i)
        #pragma unroll
        for (int j = 0; j < 4; ++j)
            acc[i][j][0] = acc[i][j][1] = acc[i][j][2] = acc[i][j][3] = 0.0f;

    int nc = K >> 5;

    // prologue: stages 0,1
    {
        uint32_t b0 = sb;
        CP16(b0 + so0,         gAh + go0);  CP16(b0 + so1,         gAh + go1);
        CP16(b0 + 8192 + so0,  gAl + go0);  CP16(b0 + 8192 + so1,  gAl + go1);
        CP16(b0 + 16384 + so0, gBh + go0);  CP16(b0 + 16384 + so1, gBh + go1);
        CP16(b0 + 24576 + so0, gBl + go0);  CP16(b0 + 24576 + so1, gBl + go1);
        CP_COMMIT();
        if (nc > 1) {
            uint32_t b1 = sb + GEMM_STG;
            CP16(b1 + so0,         gAh + 32 + go0);  CP16(b1 + so1,         gAh + 32 + go1);
            CP16(b1 + 8192 + so0,  gAl + 32 + go0);  CP16(b1 + 8192 + so1,  gAl + 32 + go1);
            CP16(b1 + 16384 + so0, gBh + 32 + go0);  CP16(b1 + 16384 + so1, gBh + 32 + go1);
            CP16(b1 + 24576 + so0, gBl + 32 + go0);  CP16(b1 + 24576 + so1, gBl + 32 + go1);
            CP_COMMIT();
        }
    }

    // ldmatrix lane geometry
    int a_row = ln & 15;
    int a_k8  = ln >> 4;
    int gq    = ln >> 3;
    int b_row = ((gq >> 1) << 3) + (ln & 7);
    int b_k8  = gq & 1;

    int stage = 0;
    for (int c = 0; c < nc; ++c) {
        if (c + 1 < nc) { CP_WAIT1(); } else { CP_WAIT0(); }
        __syncthreads();

        if (c + 2 < nc) {
            int ns = stage + 2; if (ns >= 3) ns -= 3;
            uint32_t nb = sb + ns * GEMM_STG;
            long ko = (long)(c + 2) * 32;
            CP16(nb + so0,         gAh + ko + go0);  CP16(nb + so1,         gAh + ko + go1);
            CP16(nb + 8192 + so0,  gAl + ko + go0);  CP16(nb + 8192 + so1,  gAl + ko + go1);
            CP16(nb + 16384 + so0, gBh + ko + go0);  CP16(nb + 16384 + so1, gBh + ko + go1);
            CP16(nb + 24576 + so0, gBl + ko + go0);  CP16(nb + 24576 + so1, gBl + ko + go1);
            CP_COMMIT();
        }

        uint32_t uAh = sb + stage * GEMM_STG;
        uint32_t uAl = uAh + 8192;
        uint32_t uBh = uAh + 16384;
        uint32_t uBl = uAh + 24576;

        #pragma unroll
        for (int kh = 0; kh < 2; ++kh) {
            uint32_t ah[4][4], al[4][4], bh[4][2], bl[4][2];

            #pragma unroll
            for (int mt = 0; mt < 4; ++mt) {
                int row = wm * 64 + mt * 16 + a_row;
                uint32_t off = swz(row, kh * 2 + a_k8);
                LDSM_X4(ah[mt][0], ah[mt][1], ah[mt][2], ah[mt][3], uAh + off);
                LDSM_X4(al[mt][0], al[mt][1], al[mt][2], al[mt][3], uAl + off);
            }
            #pragma unroll
            for (int np = 0; np < 2; ++np) {
                int row = wn * 32 + np * 16 + b_row;
                uint32_t off = swz(row, kh * 2 + b_k8);
                uint32_t r0, r1, r2, r3;
                LDSM_X4(r0, r1, r2, r3, uBh + off);
                bh[np * 2][0] = r0; bh[np * 2][1] = r1;
                bh[np * 2 + 1][0] = r2; bh[np * 2 + 1][1] = r3;
                LDSM_X4(r0, r1, r2, r3, uBl + off);
                bl[np * 2][0] = r0; bl[np * 2][1] = r1;
                bl[np * 2 + 1][0] = r2; bl[np * 2 + 1][1] = r3;
            }

            #pragma unroll
            for (int mt = 0; mt < 4; ++mt)
                #pragma unroll
                for (int nt = 0; nt < 4; ++nt)
                    MMA_BF16(acc[mt][nt], ah[mt], bh[nt]);
            #pragma unroll
            for (int mt = 0; mt < 4; ++mt)
                #pragma unroll
                for (int nt = 0; nt < 4; ++nt)
                    MMA_BF16(acc[mt][nt], al[mt], bh[nt]);
            #pragma unroll
            for (int mt = 0; mt < 4; ++mt)
                #pragma unroll
                for (int nt = 0; nt < 4; ++nt)
                    MMA_BF16(acc[mt][nt], ah[mt], bl[nt]);
        }

        ++stage; if (stage == 3) stage = 0;
    }

    // epilogue
    int er = ln >> 2;
    int ec = (ln & 3) << 1;
    #pragma unroll
    for (int mt = 0; mt < 4; ++mt) {
        #pragma unroll
        for (int nt = 0; nt < 4; ++nt) {
            long row0 = bm + wm * 64 + mt * 16 + er;
            long col  = bn + wn * 32 + nt * 8 + ec;
            #pragma unroll
            for (int hrow = 0; hrow < 2; ++hrow) {
                long off = (row0 + hrow * 8) * (long)N + col;
                float vx = acc[mt][nt][hrow * 2 + 0];
                float vy = acc[mt][nt][hrow * 2 + 1];
                if (EPI == EPI_SILU) {
                    vx = vx / (1.0f + __expf(-vx));
                    vy = vy / (1.0f + __expf(-vy));
                    __nv_bfloat16 hx = __float2bfloat16(vx);
                    __nv_bfloat16 hy = __float2bfloat16(vy);
                    *(uint32_t*)(Chi + off) = pack_bf2(hx, hy);
                    *(uint32_t*)(Clo + off) = pack_bf2(
                        __float2bfloat16(vx - __bfloat162float(hx)),
                        __float2bfloat16(vy - __bfloat162float(hy)));
                } else {
                    if (EPI == EPI_RES) {
                        float2 rr = *(const float2*)(R + off);
                        vx += rr.x; vy += rr.y;
                    }
                    float2 v; v.x = vx; v.y = vy;
                    *(float2*)(C + off) = v;
                }
            }
        }
    }
}

// ---------------------------------------------------------------------------
// RoPE applied in place to q and k segments of g_qkv.
// ---------------------------------------------------------------------------
__global__ void rope_kernel(float* __restrict__ qkv)
{
    int idx = blockIdx.x * blockDim.x + threadIdx.x;
    int j  = idx & 31;
    int hh = (idx >> 5) & 15;
    int s  = (idx >> 9) & 1;
    int l  = (idx >> 10) & 2047;
    int b  = idx >> 21;

    double dinv = exp(-(double)j * (9.210340371976184 / 32.0));
    float  invf = (float)dinv;
    float  fr   = (float)l * invf;
    float sn, cs;
    sincosf(fr, &sn, &cs);

    long base = (long)(b * L_ + l) * D3 + s * D_ + hh * HD_ + j;
    float x1 = qkv[base];
    float x2 = qkv[base + 32];
    qkv[base]      = x1 * cs - x2 * sn;
    qkv[base + 32] = x2 * cs + x1 * sn;
}

// ---------------------------------------------------------------------------
// Flash attention, fp32 (epilogue now writes bf16 hi/lo for the out-proj GEMM)
// ---------------------------------------------------------------------------
#define FLASH_SMEM (384 * 68 * 4)

__global__ void __launch_bounds__(256) flash_kernel(
    const float* __restrict__ qkv,
    u16* __restrict__ out_hi, u16* __restrict__ out_lo)
{
    extern __shared__ float sm[];
    float (*Qs)[68] = (float(*)[68])(sm);
    float (*Ks)[68] = (float(*)[68])(sm + 128 * 68);
    float (*Vs)[68] = (float(*)[68])(sm + 192 * 68);
    float (*Ps)[68] = (float(*)[68])(sm + 256 * 68);

    int t  = threadIdx.x;
    int tx = t & 15, ty = t >> 4;
    int q0 = blockIdx.x << 7;
    int h  = blockIdx.y;
    int b  = blockIdx.z;

    const float* base = qkv + (long)b * L_ * D3 + h * HD_;

    for (int i = t; i < 128 * 16; i += 256) {
        int r = i >> 4, c4 = (i & 15) << 2;
        float4 v = *(const float4*)(base + (long)(q0 + r) * D3 + c4);
        v.x *= 0.125f; v.y *= 0.125f; v.z *= 0.125f; v.w *= 0.125f;
        *(float4*)&Qs[r][c4] = v;
    }

    float m[8], l[8], o[8][4];
    #pragma unroll
    for (int i = 0; i < 8; ++i) {
        m[i] = -1e30f; l[i] = 0.0f;
        o[i][0] = o[i][1] = o[i][2] = o[i][3] = 0.0f;
    }
    __syncthreads();

    for (int kt = 0; kt < 32; ++kt) {
        int k0 = kt << 6;
        for (int i = t; i < 64 * 16; i += 256) {
            int r = i >> 4, c4 = (i & 15) << 2;
            *(float4*)&Ks[r][c4] =
                *(const float4*)(base + D_     + (long)(k0 + r) * D3 + c4);
            *(float4*)&Vs[r][c4] =
                *(const float4*)(base + 2 * D_ + (long)(k0 + r) * D3 + c4);
        }
        __syncthreads();

        float s[8][4];
        #pragma unroll
        for (int i = 0; i < 8; ++i)
            s[i][0] = s[i][1] = s[i][2] = s[i][3] = 0.0f;

        #pragma unroll 4
        for (int d4 = 0; d4 < 64; d4 += 4) {
            float4 k0f = *(const float4*)&Ks[tx     ][d4];
            float4 k1f = *(const float4*)&Ks[tx + 16][d4];
            float4 k2f = *(const float4*)&Ks[tx + 32][d4];
            float4 k3f = *(const float4*)&Ks[tx + 48][d4];
            #pragma unroll
            for (int i = 0; i < 8; ++i) {
                float4 qf = *(const float4*)&Qs[ty * 8 + i][d4];
                s[i][0] += qf.x * k0f.x + qf.y * k0f.y + qf.z * k0f.z + qf.w * k0f.w;
                s[i][1] += qf.x * k1f.x + qf.y * k1f.y + qf.z * k1f.z + qf.w * k1f.w;
                s[i][2] += qf.x * k2f.x + qf.y * k2f.y + qf.z * k2f.z + qf.w * k2f.w;
                s[i][3] += qf.x * k3f.x + qf.y * k3f.y + qf.z * k3f.z + qf.w * k3f.w;
            }
        }

        #pragma unroll
        for (int i = 0; i < 8; ++i) {
            float mx = fmaxf(fmaxf(s[i][0], s[i][1]), fmaxf(s[i][2], s[i][3]));
            #pragma unroll
            for (int off = 8; off > 0; off >>= 1)
                mx = fmaxf(mx, __shfl_xor_sync(0xffffffffu, mx, off));
            float mn    = fmaxf(m[i], mx);
            float alpha = __expf(m[i] - mn);
            m[i] = mn;
            float p0 = __expf(s[i][0] - mn), p1 = __expf(s[i][1] - mn);
            float p2 = __expf(s[i][2] - mn), p3 = __expf(s[i][3] - mn);
            float sum = p0 + p1 + p2 + p3;
            #pragma unroll
            for (int off = 8; off > 0; off >>= 1)
                sum += __shfl_xor_sync(0xffffffffu, sum, off);
            l[i] = l[i] * alpha + sum;
            o[i][0] *= alpha; o[i][1] *= alpha; o[i][2] *= alpha; o[i][3] *= alpha;
            int r = ty * 8 + i;
            Ps[r][tx] = p0; Ps[r][tx + 16] = p1; Ps[r][tx + 32] = p2; Ps[r][tx + 48] = p3;
        }
        __syncthreads();

        #pragma unroll 8
        for (int k = 0; k < 64; ++k) {
            float4 vv = *(const float4*)&Vs[k][tx << 2];
            #pragma unroll
            for (int i = 0; i < 8; ++i) {
                float p = Ps[ty * 8 + i][k];
                o[i][0] += p * vv.x; o[i][1] += p * vv.y;
                o[i][2] += p * vv.z; o[i][3] += p * vv.w;
            }
        }
        __syncthreads();
    }

    #pragma unroll
    for (int i = 0; i < 8; ++i) {
        float inv = 1.0f / l[i];
        float4 v;
        v.x = o[i][0] * inv; v.y = o[i][1] * inv;
        v.z = o[i][2] * inv; v.w = o[i][3] * inv;
        long row  = (long)b * L_ + q0 + ty * 8 + i;
        long eoff = row * D_ + h * HD_ + (tx << 2);
        uint2 hv, lv;
        split4(v, hv, lv);
        *(uint2*)(out_hi + eoff) = hv;
        *(uint2*)(out_lo + eoff) = lv;
    }
}

// ---------------------------------------------------------------------------
// kernel_launch
// ---------------------------------------------------------------------------
extern "C" void kernel_launch(void* const* d_in, const int* in_sizes, int n_in,
                              void* d_out, int out_size)
{
    const float* zH     = (const float*)d_in[0];
    const float* zL     = (const float*)d_in[1];
    const float* w_qkv  = (const float*)d_in[2];
    const float* w_out  = (const float*)d_in[3];
    const float* w_ffn1 = (const float*)d_in[4];
    const float* w_ffn2 = (const float*)d_in[5];
    const float* g1     = (const float*)d_in[6];
    const float* g2     = (const float*)d_in[7];
    float* out = (float*)d_out;

    float *px, *pqkv;
    u16 *phh, *phl, *paoh, *paol, *pmh, *pml;
    u16 *pw1h, *pw1l, *pw2h, *pw2l, *pw3h, *pw3l, *pw4h, *pw4l;
    cudaGetSymbolAddress((void**)&px,   g_x);
    cudaGetSymbolAddress((void**)&pqkv, g_qkv);
    cudaGetSymbolAddress((void**)&phh,  g_h_hi);
    cudaGetSymbolAddress((void**)&phl,  g_h_lo);
    cudaGetSymbolAddress((void**)&paoh, g_ao_hi);
    cudaGetSymbolAddress((void**)&paol, g_ao_lo);
    cudaGetSymbolAddress((void**)&pmh,  g_mid_hi);
    cudaGetSymbolAddress((void**)&pml,  g_mid_lo);
    cudaGetSymbolAddress((void**)&pw1h, g_w1_hi);
    cudaGetSymbolAddress((void**)&pw1l, g_w1_lo);
    cudaGetSymbolAddress((void**)&pw2h, g_w2_hi);
    cudaGetSymbolAddress((void**)&pw2l, g_w2_lo);
    cudaGetSymbolAddress((void**)&pw3h, g_w3_hi);
    cudaGetSymbolAddress((void**)&pw3l, g_w3_lo);
    cudaGetSymbolAddress((void**)&pw4h, g_w4_hi);
    cudaGetSymbolAddress((void**)&pw4l, g_w4_lo);

    cudaFuncSetAttribute(flash_kernel,
                         cudaFuncAttributeMaxDynamicSharedMemorySize, FLASH_SMEM);
    cudaFuncSetAttribute(gemm_bf3<EPI_NONE>,
                         cudaFuncAttributeMaxDynamicSharedMemorySize, GEMM_SMEM);
    cudaFuncSetAttribute(gemm_bf3<EPI_SILU>,
                         cudaFuncAttributeMaxDynamicSharedMemorySize, GEMM_SMEM);
    cudaFuncSetAttribute(gemm_bf3<EPI_RES>,
                         cudaFuncAttributeMaxDynamicSharedMemorySize, GEMM_SMEM);

    // 0. weight split (bf16 hi/lo), once per launch
    splitw_kernel<<<(D3 * D_) / 1024, 256>>>(w_qkv,  pw1h, pw1l);
    splitw_kernel<<<(D_ * D_) / 1024, 256>>>(w_out,  pw2h, pw2l);
    splitw_kernel<<<(D4 * D_) / 1024, 256>>>(w_ffn1, pw3h, pw3l);
    splitw_kernel<<<(D_ * D4) / 1024, 256>>>(w_ffn2, pw4h, pw4l);

    // 1. x = zH + zL ; h = rmsnorm(x) * g1  (bf16 split)
    rmsnorm_kernel<true><<<ROWS, 256>>>(zH, zL, g1, px, phh, phl);

    // 2. qkv = h @ w_qkv^T                [4096, 3072] fp32
    gemm_bf3<EPI_NONE><<<dim3(D3 / 128, ROWS / 128), 256, GEMM_SMEM>>>(
        phh, phl, pw1h, pw1l, nullptr, pqkv, nullptr, nullptr, ROWS, D3, D_);

    // 3. RoPE on q, k (in place)
    rope_kernel<<<(B_ * L_ * 2 * H_ * 32) / 256, 256>>>(pqkv);

    // 4. attention -> ao (bf16 split)
    flash_kernel<<<dim3(L_ / 128, H_, B_), 256, FLASH_SMEM>>>(pqkv, paoh, paol);

    // 5. x2 = x + ao @ w_out^T            (in place into g_x)
    gemm_bf3<EPI_RES><<<dim3(D_ / 128, ROWS / 128), 256, GEMM_SMEM>>>(
        paoh, paol, pw2h, pw2l, px, px, nullptr, nullptr, ROWS, D_, D_);

    // 6. h2 = rmsnorm(x2) * g2 (bf16 split)
    rmsnorm_kernel<false><<<ROWS, 256>>>(px, nullptr, g2, nullptr, phh, phl);

    // 7. mid = silu(h2 @ w_ffn1^T)        [4096, 4096] bf16 split
    gemm_bf3<EPI_SILU><<<dim3(D4 / 128, ROWS / 128), 256, GEMM_SMEM>>>(
        phh, phl, pw3h, pw3l, nullptr, nullptr, pmh, pml, ROWS, D4, D_);

    // 8. out = x2 + mid @ w_ffn2^T        [4096, 1024] fp32, K = 4096
    gemm_bf3<EPI_RES><<<dim3(D_ / 128, ROWS / 128), 256, GEMM_SMEM>>>(
        pmh, pml, pw4h, pw4l, px, out, nullptr, nullptr, ROWS, D_, D4);
}

// round 17
// speedup vs baseline: 2.6977x; 1.4193x over previous
#include <cuda_runtime.h>
#include <cuda_bf16.h>
#include <math.h>
#include <cstdint>

// Problem constants
#define B_   2
#define L_   2048
#define D_   1024
#define H_   16
#define HD_  64
#define ROWS (B_ * L_)          // 4096
#define D3   (3 * D_)           // 3072
#define D4   (4 * D_)           // 4096

typedef unsigned short u16;

// ---------------------------------------------------------------------------
// Scratch (static __device__ arrays — no allocation allowed)
// ---------------------------------------------------------------------------
__device__ float g_x  [ROWS * D_];   // residual stream (fp32)
__device__ float g_qkv[ROWS * D3];   // qkv (fp32, from GEMM)

// rope'd q,k + v in head-major layout [s][b][h][l][64], bf16 hi/lo
__device__ u16 g_att_hi[3 * B_ * H_ * L_ * HD_];
__device__ u16 g_att_lo[3 * B_ * H_ * L_ * HD_];

__device__ u16 g_h_hi [ROWS * D_],  g_h_lo [ROWS * D_];
__device__ u16 g_ao_hi[ROWS * D_],  g_ao_lo[ROWS * D_];
__device__ u16 g_mid_hi[ROWS * D4], g_mid_lo[ROWS * D4];

__device__ u16 g_w1_hi[D3 * D_], g_w1_lo[D3 * D_];
__device__ u16 g_w2_hi[D_ * D_], g_w2_lo[D_ * D_];
__device__ u16 g_w3_hi[D4 * D_], g_w3_lo[D4 * D_];
__device__ u16 g_w4_hi[D_ * D4], g_w4_lo[D_ * D4];

// ---------------------------------------------------------------------------
// PTX helpers (baseline ISA only — target is compute_103, no tcgen05)
// ---------------------------------------------------------------------------
__device__ __forceinline__ uint32_t smem_u32(const void* p) {
    uint32_t a;
    asm("{ .reg .u64 t; cvta.to.shared.u64 t, %1; cvt.u32.u64 %0, t; }"
        : "=r"(a) : "l"(p));
    return a;
}

#define LDSM_X4(R0, R1, R2, R3, ADDR)                                         \
    asm volatile("ldmatrix.sync.aligned.m8n8.x4.shared.b16 {%0,%1,%2,%3}, [%4];" \
                 : "=r"(R0), "=r"(R1), "=r"(R2), "=r"(R3) : "r"(ADDR))

#define LDSM_X4_T(R0, R1, R2, R3, ADDR)                                       \
    asm volatile("ldmatrix.sync.aligned.m8n8.x4.trans.shared.b16 {%0,%1,%2,%3}, [%4];" \
                 : "=r"(R0), "=r"(R1), "=r"(R2), "=r"(R3) : "r"(ADDR))

#define MMA_BF16(c, a, b)                                                     \
    asm volatile("mma.sync.aligned.m16n8k16.row.col.f32.bf16.bf16.f32 "       \
                 "{%0,%1,%2,%3}, {%4,%5,%6,%7}, {%8,%9}, {%0,%1,%2,%3};"      \
                 : "+f"((c)[0]), "+f"((c)[1]), "+f"((c)[2]), "+f"((c)[3])     \
                 : "r"((a)[0]), "r"((a)[1]), "r"((a)[2]), "r"((a)[3]),        \
                   "r"((b)[0]), "r"((b)[1]))

#define CP16(s, g)  asm volatile("cp.async.cg.shared.global [%0], [%1], 16;" \
                                 :: "r"(s), "l"(g))
#define CP_COMMIT() asm volatile("cp.async.commit_group;")
#define CP_WAIT1()  asm volatile("cp.async.wait_group 1;")
#define CP_WAIT0()  asm volatile("cp.async.wait_group 0;")

// ---------------------------------------------------------------------------
// bf16 hi/lo split helpers
// ---------------------------------------------------------------------------
__device__ __forceinline__ uint32_t pack_bf2(__nv_bfloat16 a, __nv_bfloat16 b) {
    return (uint32_t)__bfloat16_as_ushort(a) |
           ((uint32_t)__bfloat16_as_ushort(b) << 16);
}

__device__ __forceinline__ void split4(float4 v, uint2& hv, uint2& lv) {
    __nv_bfloat16 h0 = __float2bfloat16(v.x), h1 = __float2bfloat16(v.y);
    __nv_bfloat16 h2 = __float2bfloat16(v.z), h3 = __float2bfloat16(v.w);
    hv.x = pack_bf2(h0, h1);
    hv.y = pack_bf2(h2, h3);
    __nv_bfloat16 l0 = __float2bfloat16(v.x - __bfloat162float(h0));
    __nv_bfloat16 l1 = __float2bfloat16(v.y - __bfloat162float(h1));
    __nv_bfloat16 l2 = __float2bfloat16(v.z - __bfloat162float(h2));
    __nv_bfloat16 l3 = __float2bfloat16(v.w - __bfloat162float(h3));
    lv.x = pack_bf2(l0, l1);
    lv.y = pack_bf2(l2, l3);
}

__device__ __forceinline__ void split2(float x, float y,
                                       uint32_t& hv, uint32_t& lv) {
    __nv_bfloat16 hx = __float2bfloat16(x), hy = __float2bfloat16(y);
    hv = pack_bf2(hx, hy);
    lv = pack_bf2(__float2bfloat16(x - __bfloat162float(hx)),
                  __float2bfloat16(y - __bfloat162float(hy)));
}

// weight split: fp32 -> bf16 hi/lo
__global__ void splitw_kernel(const float* __restrict__ w,
                              u16* __restrict__ hi, u16* __restrict__ lo)
{
    long i = (long)blockIdx.x * blockDim.x + threadIdx.x;
    float4 v = ((const float4*)w)[i];
    uint2 hv, lv;
    split4(v, hv, lv);
    ((uint2*)hi)[i] = hv;
    ((uint2*)lo)[i] = lv;
}

// ---------------------------------------------------------------------------
// Fused (optional add) + RMSNorm -> bf16 split output.
// ---------------------------------------------------------------------------
template <bool ADD>
__global__ void rmsnorm_kernel(const float* __restrict__ A,
                               const float* __restrict__ Bp,
                               const float* __restrict__ g,
                               float* __restrict__ x_out,
                               u16* __restrict__ h_hi,
                               u16* __restrict__ h_lo)
{
    int row = blockIdx.x;
    int t   = threadIdx.x;
    long base = (long)row * D_;

    float4 x = ((const float4*)(A + base))[t];
    if (ADD) {
        float4 b = ((const float4*)(Bp + base))[t];
        x.x += b.x; x.y += b.y; x.z += b.z; x.w += b.w;
    }
    float ss = x.x * x.x + x.y * x.y + x.z * x.z + x.w * x.w;
    #pragma unroll
    for (int off = 16; off > 0; off >>= 1)
        ss += __shfl_xor_sync(0xffffffffu, ss, off);

    __shared__ float sw[8];
    if ((t & 31) == 0) sw[t >> 5] = ss;
    __syncthreads();
    float tot = sw[0] + sw[1] + sw[2] + sw[3] + sw[4] + sw[5] + sw[6] + sw[7];
    float r = rsqrtf(tot * (1.0f / (float)D_) + 1e-6f);

    float4 gg = ((const float4*)g)[t];
    float4 h;
    h.x = x.x * r * gg.x;  h.y = x.y * r * gg.y;
    h.z = x.z * r * gg.z;  h.w = x.w * r * gg.w;

    if (ADD) ((float4*)(x_out + base))[t] = x;
    uint2 hv, lv;
    split4(h, hv, lv);
    ((uint2*)h_hi)[row * 256 + t] = hv;
    ((uint2*)h_lo)[row * 256 + t] = lv;
}

// ---------------------------------------------------------------------------
// bf16-split tensor-core GEMM (unchanged, passing @ ~HMMA roofline)
// ---------------------------------------------------------------------------
#define EPI_NONE 0
#define EPI_SILU 1
#define EPI_RES  2

#define GEMM_STG   32768
#define GEMM_SMEM  (3 * GEMM_STG)

__device__ __forceinline__ uint32_t swz(int row, int u) {
    return (uint32_t)(row * 64 + ((u ^ ((row >> 1) & 3)) << 4));
}

template <int EPI>
__global__ void __launch_bounds__(256) gemm_bf3(
    const u16* __restrict__ Ah, const u16* __restrict__ Al,
    const u16* __restrict__ Bh, const u16* __restrict__ Bl,
    const float* __restrict__ R, float* __restrict__ C,
    u16* __restrict__ Chi, u16* __restrict__ Clo,
    int M, int N, int K)
{
    extern __shared__ char smx[];
    uint32_t sb = smem_u32(smx);

    int t   = threadIdx.x;
    int ln  = t & 31;
    int wid = t >> 5;
    int wm  = wid >> 2;
    int wn  = wid & 3;
    int bm  = blockIdx.y << 7;
    int bn  = blockIdx.x << 7;

    int lrow = t >> 1;
    int lu0  = (t & 1) << 1;
    const u16* gAh = Ah + (long)(bm + lrow) * K;
    const u16* gAl = Al + (long)(bm + lrow) * K;
    const u16* gBh = Bh + (long)(bn + lrow) * K;
    const u16* gBl = Bl + (long)(bn + lrow) * K;
    uint32_t so0 = swz(lrow, lu0);
    uint32_t so1 = swz(lrow, lu0 + 1);
    int go0 = lu0 * 8, go1 = lu0 * 8 + 8;

    float acc[4][4][4];
    #pragma unroll
    for (int i = 0; i < 4; ++i)
        #pragma unroll
        for (int j = 0; j < 4; ++j)
            acc[i][j][0] = acc[i][j][1] = acc[i][j][2] = acc[i][j][3] = 0.0f;

    int nc = K >> 5;

    {
        uint32_t b0 = sb;
        CP16(b0 + so0,         gAh + go0);  CP16(b0 + so1,         gAh + go1);
        CP16(b0 + 8192 + so0,  gAl + go0);  CP16(b0 + 8192 + so1,  gAl + go1);
        CP16(b0 + 16384 + so0, gBh + go0);  CP16(b0 + 16384 + so1, gBh + go1);
        CP16(b0 + 24576 + so0, gBl + go0);  CP16(b0 + 24576 + so1, gBl + go1);
        CP_COMMIT();
        if (nc > 1) {
            uint32_t b1 = sb + GEMM_STG;
            CP16(b1 + so0,         gAh + 32 + go0);  CP16(b1 + so1,         gAh + 32 + go1);
            CP16(b1 + 8192 + so0,  gAl + 32 + go0);  CP16(b1 + 8192 + so1,  gAl + 32 + go1);
            CP16(b1 + 16384 + so0, gBh + 32 + go0);  CP16(b1 + 16384 + so1, gBh + 32 + go1);
            CP16(b1 + 24576 + so0, gBl + 32 + go0);  CP16(b1 + 24576 + so1, gBl + 32 + go1);
            CP_COMMIT();
        }
    }

    int a_row = ln & 15;
    int a_k8  = ln >> 4;
    int gq    = ln >> 3;
    int b_row = ((gq >> 1) << 3) + (ln & 7);
    int b_k8  = gq & 1;

    int stage = 0;
    for (int c = 0; c < nc; ++c) {
        if (c + 1 < nc) { CP_WAIT1(); } else { CP_WAIT0(); }
        __syncthreads();

        if (c + 2 < nc) {
            int ns = stage + 2; if (ns >= 3) ns -= 3;
            uint32_t nb = sb + ns * GEMM_STG;
            long ko = (long)(c + 2) * 32;
            CP16(nb + so0,         gAh + ko + go0);  CP16(nb + so1,         gAh + ko + go1);
            CP16(nb + 8192 + so0,  gAl + ko + go0);  CP16(nb + 8192 + so1,  gAl + ko + go1);
            CP16(nb + 16384 + so0, gBh + ko + go0);  CP16(nb + 16384 + so1, gBh + ko + go1);
            CP16(nb + 24576 + so0, gBl + ko + go0);  CP16(nb + 24576 + so1, gBl + ko + go1);
            CP_COMMIT();
        }

        uint32_t uAh = sb + stage * GEMM_STG;
        uint32_t uAl = uAh + 8192;
        uint32_t uBh = uAh + 16384;
        uint32_t uBl = uAh + 24576;

        #pragma unroll
        for (int kh = 0; kh < 2; ++kh) {
            uint32_t ah[4][4], al[4][4], bh[4][2], bl[4][2];

            #pragma unroll
            for (int mt = 0; mt < 4; ++mt) {
                int row = wm * 64 + mt * 16 + a_row;
                uint32_t off = swz(row, kh * 2 + a_k8);
                LDSM_X4(ah[mt][0], ah[mt][1], ah[mt][2], ah[mt][3], uAh + off);
                LDSM_X4(al[mt][0], al[mt][1], al[mt][2], al[mt][3], uAl + off);
            }
            #pragma unroll
            for (int np = 0; np < 2; ++np) {
                int row = wn * 32 + np * 16 + b_row;
                uint32_t off = swz(row, kh * 2 + b_k8);
                uint32_t r0, r1, r2, r3;
                LDSM_X4(r0, r1, r2, r3, uBh + off);
                bh[np * 2][0] = r0; bh[np * 2][1] = r1;
                bh[np * 2 + 1][0] = r2; bh[np * 2 + 1][1] = r3;
                LDSM_X4(r0, r1, r2, r3, uBl + off);
                bl[np * 2][0] = r0; bl[np * 2][1] = r1;
                bl[np * 2 + 1][0] = r2; bl[np * 2 + 1][1] = r3;
            }

            #pragma unroll
            for (int mt = 0; mt < 4; ++mt)
                #pragma unroll
                for (int nt = 0; nt < 4; ++nt)
                    MMA_BF16(acc[mt][nt], ah[mt], bh[nt]);
            #pragma unroll
            for (int mt = 0; mt < 4; ++mt)
                #pragma unroll
                for (int nt = 0; nt < 4; ++nt)
                    MMA_BF16(acc[mt][nt], al[mt], bh[nt]);
            #pragma unroll
            for (int mt = 0; mt < 4; ++mt)
                #pragma unroll
                for (int nt = 0; nt < 4; ++nt)
                    MMA_BF16(acc[mt][nt], ah[mt], bl[nt]);
        }

        ++stage; if (stage == 3) stage = 0;
    }

    int er = ln >> 2;
    int ec = (ln & 3) << 1;
    #pragma unroll
    for (int mt = 0; mt < 4; ++mt) {
        #pragma unroll
        for (int nt = 0; nt < 4; ++nt) {
            long row0 = bm + wm * 64 + mt * 16 + er;
            long col  = bn + wn * 32 + nt * 8 + ec;
            #pragma unroll
            for (int hrow = 0; hrow < 2; ++hrow) {
                long off = (row0 + hrow * 8) * (long)N + col;
                float vx = acc[mt][nt][hrow * 2 + 0];
                float vy = acc[mt][nt][hrow * 2 + 1];
                if (EPI == EPI_SILU) {
                    vx = vx / (1.0f + __expf(-vx));
                    vy = vy / (1.0f + __expf(-vy));
                    uint32_t hv, lv;
                    split2(vx, vy, hv, lv);
                    *(uint32_t*)(Chi + off) = hv;
                    *(uint32_t*)(Clo + off) = lv;
                } else {
                    if (EPI == EPI_RES) {
                        float2 rr = *(const float2*)(R + off);
                        vx += rr.x; vy += rr.y;
                    }
                    float2 v; v.x = vx; v.y = vy;
                    *(float2*)(C + off) = v;
                }
            }
        }
    }
}

// ---------------------------------------------------------------------------
// RoPE + bf16 hi/lo split into head-major layout [s][b][h][l][64].
// s = blockIdx.y (0=q rotated+scaled 1/8, 1=k rotated, 2=v passthrough).
// FIXED bit layout: j[0:5) hh[5:9) l[9:20) b[20:21)  (2^21 threads, no hole)
// ---------------------------------------------------------------------------
__global__ void ropecvt_kernel(const float* __restrict__ qkv,
                               u16* __restrict__ att_hi,
                               u16* __restrict__ att_lo)
{
    int i = blockIdx.x * blockDim.x + threadIdx.x;
    int s  = blockIdx.y;
    int j  = i & 31;
    int hh = (i >> 5) & 15;
    int l  = (i >> 9) & 2047;
    int b  = i >> 20;

    long src = (long)(b * L_ + l) * D3 + s * D_ + hh * HD_ + j;
    float x1 = qkv[src];
    float x2 = qkv[src + 32];

    float y1, y2;
    if (s < 2) {
        double dinv = exp(-(double)j * (9.210340371976184 / 32.0));
        float fr = (float)l * (float)dinv;
        float sn, cs;
        sincosf(fr, &sn, &cs);
        y1 = x1 * cs - x2 * sn;
        y2 = x2 * cs + x1 * sn;
        if (s == 0) { y1 *= 0.125f; y2 *= 0.125f; }
    } else {
        y1 = x1; y2 = x2;
    }

    long dst = ((((long)s * B_ + b) * H_ + hh) * L_ + l) * HD_ + j;
    __nv_bfloat16 h1 = __float2bfloat16(y1);
    __nv_bfloat16 h2 = __float2bfloat16(y2);
    att_hi[dst]      = __bfloat16_as_ushort(h1);
    att_hi[dst + 32] = __bfloat16_as_ushort(h2);
    att_lo[dst]      = __bfloat16_as_ushort(__float2bfloat16(y1 - __bfloat162float(h1)));
    att_lo[dst + 32] = __bfloat16_as_ushort(__float2bfloat16(y2 - __bfloat162float(h2)));
}

// ---------------------------------------------------------------------------
// Flash attention v3: bf16 hi/lo split 3-term mma.sync (FA2 structure).
// CTA: 128 q-rows x (b,h); 8 warps x 16 q-rows; online softmax in registers.
// smem: Qh/Ql 32KB + 2 stages x (Kh,Kl,Vh,Vl) 64KB = 96KB.
// ---------------------------------------------------------------------------
#define FL_SMEM (32768 + 2 * 32768)

__device__ __forceinline__ uint32_t swzf(int row, int c) {
    return (uint32_t)(row * 128 + ((c ^ (row & 7)) << 4));
}

__global__ void __launch_bounds__(256) flash_bf3(
    const u16* __restrict__ att_hi, const u16* __restrict__ att_lo,
    u16* __restrict__ out_hi, u16* __restrict__ out_lo)
{
    extern __shared__ char smx[];
    uint32_t sQh = smem_u32(smx);
    uint32_t sQl = sQh + 16384;
    uint32_t sKV = sQh + 32768;      // + stage*32768: Kh, Kl, Vh, Vl (8KB each)

    int t   = threadIdx.x;
    int ln  = t & 31;
    int wid = t >> 5;
    int q0  = blockIdx.x << 7;
    int h   = blockIdx.y;
    int b   = blockIdx.z;

    long qoff = (((long)(0 * B_ + b) * H_ + h) * L_) * HD_;
    long koff = (((long)(1 * B_ + b) * H_ + h) * L_) * HD_;
    long voff = (((long)(2 * B_ + b) * H_ + h) * L_) * HD_;

    // prologue: Q hi/lo (128x64)
    #pragma unroll
    for (int i = 0; i < 4; ++i) {
        int cid = t + i * 256;
        int row = cid >> 3, c = cid & 7;
        long g = qoff + (long)(q0 + row) * HD_ + c * 8;
        CP16(sQh + swzf(row, c), att_hi + g);
        CP16(sQl + swzf(row, c), att_lo + g);
    }
    CP_COMMIT();
    // K/V stage 0
    #pragma unroll
    for (int i = 0; i < 2; ++i) {
        int cid = t + i * 256;
        int row = cid >> 3, c = cid & 7;
        uint32_t so = swzf(row, c);
        long gk = koff + (long)row * HD_ + c * 8;
        long gv = voff + (long)row * HD_ + c * 8;
        CP16(sKV + so,         att_hi + gk);
        CP16(sKV + 8192 + so,  att_lo + gk);
        CP16(sKV + 16384 + so, att_hi + gv);
        CP16(sKV + 24576 + so, att_lo + gv);
    }
    CP_COMMIT();

    // state
    float m0 = -1e30f, m1 = -1e30f, l0 = 0.0f, l1 = 0.0f;
    float o[8][4];
    #pragma unroll
    for (int j = 0; j < 8; ++j)
        o[j][0] = o[j][1] = o[j][2] = o[j][3] = 0.0f;

    uint32_t qh[4][4];               // Q-hi fragments persist
    int gq = ln >> 3;

    for (int kt = 0; kt < 32; ++kt) {
        CP_WAIT0();
        __syncthreads();

        if (kt == 0) {
            #pragma unroll
            for (int kk = 0; kk < 4; ++kk) {
                int row = wid * 16 + (ln & 15);
                uint32_t off = swzf(row, kk * 2 + (ln >> 4));
                LDSM_X4(qh[kk][0], qh[kk][1], qh[kk][2], qh[kk][3], sQh + off);
            }
        }

        int stage = kt & 1;
        uint32_t uKh = sKV + stage * 32768;
        uint32_t uKl = uKh + 8192;
        uint32_t uVh = uKh + 16384;
        uint32_t uVl = uKh + 24576;

        // prefetch next K/V stage
        if (kt + 1 < 32) {
            uint32_t nB = sKV + (stage ^ 1) * 32768;
            long kadv = (long)(kt + 1) * 64 * HD_;
            #pragma unroll
            for (int i = 0; i < 2; ++i) {
                int cid = t + i * 256;
                int row = cid >> 3, c = cid & 7;
                uint32_t so = swzf(row, c);
                long gk = koff + kadv + (long)row * HD_ + c * 8;
                long gv = voff + kadv + (long)row * HD_ + c * 8;
                CP16(nB + so,         att_hi + gk);
                CP16(nB + 8192 + so,  att_lo + gk);
                CP16(nB + 16384 + so, att_hi + gv);
                CP16(nB + 24576 + so, att_lo + gv);
            }
            CP_COMMIT();
        }

        // ---- S = Q K^T, 3-term split ----
        float s[8][4];
        #pragma unroll
        for (int j = 0; j < 8; ++j)
            s[j][0] = s[j][1] = s[j][2] = s[j][3] = 0.0f;

        #pragma unroll
        for (int kk = 0; kk < 4; ++kk) {
            uint32_t ql[4];
            {
                int row = wid * 16 + (ln & 15);
                uint32_t off = swzf(row, kk * 2 + (ln >> 4));
                LDSM_X4(ql[0], ql[1], ql[2], ql[3], sQl + off);
            }
            #pragma unroll
            for (int npg = 0; npg < 4; ++npg) {
                int row = npg * 16 + ((gq >> 1) << 3) + (ln & 7);
                uint32_t off = swzf(row, kk * 2 + (gq & 1));
                uint32_t k0, k1, k2, k3;
                LDSM_X4(k0, k1, k2, k3, uKh + off);
                uint32_t kh0[2] = { k0, k1 };
                uint32_t kh1[2] = { k2, k3 };
                LDSM_X4(k0, k1, k2, k3, uKl + off);
                uint32_t kl0[2] = { k0, k1 };
                uint32_t kl1[2] = { k2, k3 };
                MMA_BF16(s[npg * 2],     qh[kk], kh0);
                MMA_BF16(s[npg * 2 + 1], qh[kk], kh1);
                MMA_BF16(s[npg * 2],     ql,     kh0);
                MMA_BF16(s[npg * 2 + 1], ql,     kh1);
                MMA_BF16(s[npg * 2],     qh[kk], kl0);
                MMA_BF16(s[npg * 2 + 1], qh[kk], kl1);
            }
        }

        // ---- online softmax (rows r0 = ln>>2, r0+8) ----
        float mx0 = -1e30f, mx1 = -1e30f;
        #pragma unroll
        for (int j = 0; j < 8; ++j) {
            mx0 = fmaxf(mx0, fmaxf(s[j][0], s[j][1]));
            mx1 = fmaxf(mx1, fmaxf(s[j][2], s[j][3]));
        }
        mx0 = fmaxf(mx0, __shfl_xor_sync(0xffffffffu, mx0, 1));
        mx0 = fmaxf(mx0, __shfl_xor_sync(0xffffffffu, mx0, 2));
        mx1 = fmaxf(mx1, __shfl_xor_sync(0xffffffffu, mx1, 1));
        mx1 = fmaxf(mx1, __shfl_xor_sync(0xffffffffu, mx1, 2));

        float mn0 = fmaxf(m0, mx0), mn1 = fmaxf(m1, mx1);
        float a0 = __expf(m0 - mn0), a1 = __expf(m1 - mn1);
        m0 = mn0; m1 = mn1;

        float sm0 = 0.0f, sm1 = 0.0f;
        #pragma unroll
        for (int j = 0; j < 8; ++j) {
            s[j][0] = __expf(s[j][0] - mn0);
            s[j][1] = __expf(s[j][1] - mn0);
            s[j][2] = __expf(s[j][2] - mn1);
            s[j][3] = __expf(s[j][3] - mn1);
            sm0 += s[j][0] + s[j][1];
            sm1 += s[j][2] + s[j][3];
        }
        sm0 += __shfl_xor_sync(0xffffffffu, sm0, 1);
        sm0 += __shfl_xor_sync(0xffffffffu, sm0, 2);
        sm1 += __shfl_xor_sync(0xffffffffu, sm1, 1);
        sm1 += __shfl_xor_sync(0xffffffffu, sm1, 2);
        l0 = l0 * a0 + sm0;
        l1 = l1 * a1 + sm1;

        #pragma unroll
        for (int j = 0; j < 8; ++j) {
            o[j][0] *= a0; o[j][1] *= a0;
            o[j][2] *= a1; o[j][3] *= a1;
        }

        // ---- O += P V, 3-term split (P split in registers) ----
        #pragma unroll
        for (int kk = 0; kk < 4; ++kk) {
            uint32_t pah[4], pal[4];
            split2(s[2 * kk][0],     s[2 * kk][1],     pah[0], pal[0]);
            split2(s[2 * kk][2],     s[2 * kk][3],     pah[1], pal[1]);
            split2(s[2 * kk + 1][0], s[2 * kk + 1][1], pah[2], pal[2]);
            split2(s[2 * kk + 1][2], s[2 * kk + 1][3], pah[3], pal[3]);
            #pragma unroll
            for (int npg = 0; npg < 4; ++npg) {
                int vrow = kk * 16 + ((gq & 1) << 3) + (ln & 7);
                uint32_t off = swzf(vrow, npg * 2 + (gq >> 1));
                uint32_t v0, v1, v2, v3;
                LDSM_X4_T(v0, v1, v2, v3, uVh + off);
                uint32_t vh0[2] = { v0, v1 };
                uint32_t vh1[2] = { v2, v3 };
                LDSM_X4_T(v0, v1, v2, v3, uVl + off);
                uint32_t vl0[2] = { v0, v1 };
                uint32_t vl1[2] = { v2, v3 };
                MMA_BF16(o[npg * 2],     pah, vh0);
                MMA_BF16(o[npg * 2 + 1], pah, vh1);
                MMA_BF16(o[npg * 2],     pal, vh0);
                MMA_BF16(o[npg * 2 + 1], pal, vh1);
                MMA_BF16(o[npg * 2],     pah, vl0);
                MMA_BF16(o[npg * 2 + 1], pah, vl1);
            }
        }

        __syncthreads();
    }

    // ---- epilogue: O / l, bf16 split write ----
    float il0 = 1.0f / l0, il1 = 1.0f / l1;
    long row0 = (long)b * L_ + q0 + wid * 16 + (ln >> 2);
    #pragma unroll
    for (int j = 0; j < 8; ++j) {
        int d = h * HD_ + j * 8 + ((ln & 3) << 1);
        uint32_t hv, lv;
        split2(o[j][0] * il0, o[j][1] * il0, hv, lv);
        *(uint32_t*)(out_hi + row0 * D_ + d) = hv;
        *(uint32_t*)(out_lo + row0 * D_ + d) = lv;
        split2(o[j][2] * il1, o[j][3] * il1, hv, lv);
        *(uint32_t*)(out_hi + (row0 + 8) * D_ + d) = hv;
        *(uint32_t*)(out_lo + (row0 + 8) * D_ + d) = lv;
    }
}

// ---------------------------------------------------------------------------
// kernel_launch
// ---------------------------------------------------------------------------
extern "C" void kernel_launch(void* const* d_in, const int* in_sizes, int n_in,
                              void* d_out, int out_size)
{
    const float* zH     = (const float*)d_in[0];
    const float* zL     = (const float*)d_in[1];
    const float* w_qkv  = (const float*)d_in[2];
    const float* w_out  = (const float*)d_in[3];
    const float* w_ffn1 = (const float*)d_in[4];
    const float* w_ffn2 = (const float*)d_in[5];
    const float* g1     = (const float*)d_in[6];
    const float* g2     = (const float*)d_in[7];
    float* out = (float*)d_out;

    float *px, *pqkv;
    u16 *path, *patl;
    u16 *phh, *phl, *paoh, *paol, *pmh, *pml;
    u16 *pw1h, *pw1l, *pw2h, *pw2l, *pw3h, *pw3l, *pw4h, *pw4l;
    cudaGetSymbolAddress((void**)&px,   g_x);
    cudaGetSymbolAddress((void**)&pqkv, g_qkv);
    cudaGetSymbolAddress((void**)&path, g_att_hi);
    cudaGetSymbolAddress((void**)&patl, g_att_lo);
    cudaGetSymbolAddress((void**)&phh,  g_h_hi);
    cudaGetSymbolAddress((void**)&phl,  g_h_lo);
    cudaGetSymbolAddress((void**)&paoh, g_ao_hi);
    cudaGetSymbolAddress((void**)&paol, g_ao_lo);
    cudaGetSymbolAddress((void**)&pmh,  g_mid_hi);
    cudaGetSymbolAddress((void**)&pml,  g_mid_lo);
    cudaGetSymbolAddress((void**)&pw1h, g_w1_hi);
    cudaGetSymbolAddress((void**)&pw1l, g_w1_lo);
    cudaGetSymbolAddress((void**)&pw2h, g_w2_hi);
    cudaGetSymbolAddress((void**)&pw2l, g_w2_lo);
    cudaGetSymbolAddress((void**)&pw3h, g_w3_hi);
    cudaGetSymbolAddress((void**)&pw3l, g_w3_lo);
    cudaGetSymbolAddress((void**)&pw4h, g_w4_hi);
    cudaGetSymbolAddress((void**)&pw4l, g_w4_lo);

    cudaFuncSetAttribute(flash_bf3,
                         cudaFuncAttributeMaxDynamicSharedMemorySize, FL_SMEM);
    cudaFuncSetAttribute(gemm_bf3<EPI_NONE>,
                         cudaFuncAttributeMaxDynamicSharedMemorySize, GEMM_SMEM);
    cudaFuncSetAttribute(gemm_bf3<EPI_SILU>,
                         cudaFuncAttributeMaxDynamicSharedMemorySize, GEMM_SMEM);
    cudaFuncSetAttribute(gemm_bf3<EPI_RES>,
                         cudaFuncAttributeMaxDynamicSharedMemorySize, GEMM_SMEM);

    // 0. weight split (bf16 hi/lo)
    splitw_kernel<<<(D3 * D_) / 1024, 256>>>(w_qkv,  pw1h, pw1l);
    splitw_kernel<<<(D_ * D_) / 1024, 256>>>(w_out,  pw2h, pw2l);
    splitw_kernel<<<(D4 * D_) / 1024, 256>>>(w_ffn1, pw3h, pw3l);
    splitw_kernel<<<(D_ * D4) / 1024, 256>>>(w_ffn2, pw4h, pw4l);

    // 1. x = zH + zL ; h = rmsnorm(x) * g1
    rmsnorm_kernel<true><<<ROWS, 256>>>(zH, zL, g1, px, phh, phl);

    // 2. qkv = h @ w_qkv^T            [4096, 3072] fp32
    gemm_bf3<EPI_NONE><<<dim3(D3 / 128, ROWS / 128), 256, GEMM_SMEM>>>(
        phh, phl, pw1h, pw1l, nullptr, pqkv, nullptr, nullptr, ROWS, D3, D_);

    // 3. RoPE + bf16 hi/lo split to head-major [s][b][h][l][64]
    ropecvt_kernel<<<dim3((B_ * L_ * H_ * 32) / 256, 3), 256>>>(pqkv, path, patl);

    // 4. attention -> ao (bf16 split)
    flash_bf3<<<dim3(L_ / 128, H_, B_), 256, FL_SMEM>>>(path, patl, paoh, paol);

    // 5. x2 = x + ao @ w_out^T
    gemm_bf3<EPI_RES><<<dim3(D_ / 128, ROWS / 128), 256, GEMM_SMEM>>>(
        paoh, paol, pw2h, pw2l, px, px, nullptr, nullptr, ROWS, D_, D_);

    // 6. h2 = rmsnorm(x2) * g2
    rmsnorm_kernel<false><<<ROWS, 256>>>(px, nullptr, g2, nullptr, phh, phl);

    // 7. mid = silu(h2 @ w_ffn1^T)    [4096, 4096]
    gemm_bf3<EPI_SILU><<<dim3(D4 / 128, ROWS / 128), 256, GEMM_SMEM>>>(
        phh, phl, pw3h, pw3l, nullptr, nullptr, pmh, pml, ROWS, D4, D_);

    // 8. out = x2 + mid @ w_ffn2^T    [4096, 1024], K = 4096
    gemm_bf3<EPI_RES><<<dim3(D_ / 128, ROWS / 128), 256, GEMM_SMEM>>>(
        pmh, pml, pw4h, pw4l, px, out, nullptr, nullptr, ROWS, D_, D4);
}